// round 1
// baseline (speedup 1.0000x reference)
#include <cuda_runtime.h>
#include <cuda_bf16.h>
#include <math.h>

#define N_NODES 20000
#define N_EDGES 100000
#define N_TRI   200000
#define NORB    16
#define EMB     128
#define CONV    64

typedef unsigned long long u64;

// ---------- packed f32x2 helpers (sm_103a FFMA2 path) ----------
__device__ __forceinline__ void fma2(u64 &d, u64 a, u64 b) {
    asm("fma.rn.f32x2 %0, %1, %2, %0;" : "+l"(d) : "l"(a), "l"(b));
}
__device__ __forceinline__ u64 pack2(float lo, float hi) {
    u64 r; asm("mov.b64 %0, {%1, %2};" : "=l"(r) : "f"(lo), "f"(hi)); return r;
}
__device__ __forceinline__ void unpack2(u64 v, float &lo, float &hi) {
    asm("mov.b64 {%0, %1}, %2;" : "=f"(lo), "=f"(hi) : "l"(v));
}
__device__ __forceinline__ float silu_f(float x) { return x / (1.f + __expf(-x)); }
__device__ __forceinline__ float sigmoid_f(float x) { return 1.f / (1.f + __expf(-x)); }

// ---------- scratch (device globals; no allocation allowed) ----------
__device__ float g_x1   [(size_t)N_NODES * CONV];           // h[:, :64]
__device__ float g_xksig[(size_t)N_NODES * CONV];           // sigmoid(h[:, 64:])
__device__ float g_cst2 [(size_t)N_EDGES * NORB * CONV];    // silu(silu(cst@W1)@W2)
__device__ float g_tbw  [(size_t)N_EDGES * CONV];           // segment-summed three-body weights
__device__ float g_agg  [(size_t)N_NODES * CONV];           // segment-summed messages

// ---------- zero the atomic targets ----------
__global__ void k_zero() {
    int i = blockIdx.x * blockDim.x + threadIdx.x;
    const int t1 = N_EDGES * CONV;
    const int total = t1 + N_NODES * CONV;
    if (i < total) {
        if (i < t1) g_tbw[i] = 0.f;
        else        g_agg[i - t1] = 0.f;
    }
}

// ---------- K1: node transform  h = x @ W_node + b ----------
__global__ void __launch_bounds__(128) k_node(const float* __restrict__ x,
                                              const float* __restrict__ Wn,
                                              const float* __restrict__ bn) {
    __shared__ float xs[EMB];
    int n = blockIdx.x, j = threadIdx.x;
    xs[j] = x[(size_t)n * EMB + j];
    __syncthreads();
    float acc = bn[j];
#pragma unroll 8
    for (int k = 0; k < EMB; k++)
        acc = fmaf(xs[k], Wn[k * EMB + j], acc);
    if (j < CONV) g_x1[(size_t)n * CONV + j] = acc;
    else          g_xksig[(size_t)n * CONV + (j - CONV)] = sigmoid_f(acc);
}

// ---------- K2: cst = silu(silu(cst @ W_c1) @ W_c2), 1.6M x 64 rows ----------
// 64-row tile per block, 256 threads, each thread a 4x4 micro-tile, FFMA2 pairs.
__global__ void __launch_bounds__(256) k_cst(const float* __restrict__ A,
                                             const float* __restrict__ W1,
                                             const float* __restrict__ W2) {
    __shared__ __align__(16) float Ws[4096];
    __shared__ __align__(16) float As[4096];
    int tid = threadIdx.x;
    float4* Ws4 = (float4*)Ws;
    float4* As4 = (float4*)As;
    const float4* Wg1 = (const float4*)W1;
    const float4* Ag  = (const float4*)(A + (size_t)blockIdx.x * 4096);
#pragma unroll
    for (int i = 0; i < 4; i++) {
        Ws4[tid + 256 * i] = Wg1[tid + 256 * i];
        As4[tid + 256 * i] = Ag [tid + 256 * i];
    }
    __syncthreads();

    const int tr = (tid >> 4) << 2;   // row base (0..60)
    const int tc = (tid & 15) << 2;   // col base (0..60)
    u64 acc[4][2];

    // ---- stage 1 ----
#pragma unroll
    for (int i = 0; i < 4; i++) { acc[i][0] = 0ull; acc[i][1] = 0ull; }
#pragma unroll 8
    for (int k = 0; k < 64; k++) {
        ulonglong2 w = *(const ulonglong2*)&Ws[k * 64 + tc];
#pragma unroll
        for (int i = 0; i < 4; i++) {
            float a = As[(tr + i) * 64 + k];
            u64 a2 = pack2(a, a);
            fma2(acc[i][0], a2, w.x);
            fma2(acc[i][1], a2, w.y);
        }
    }
    __syncthreads();
    // write silu(Y) back into As; refill Ws with W2
#pragma unroll
    for (int i = 0; i < 4; i++) {
        float s0, s1, s2, s3;
        unpack2(acc[i][0], s0, s1); unpack2(acc[i][1], s2, s3);
        As4[((tr + i) * 64 + tc) >> 2] =
            make_float4(silu_f(s0), silu_f(s1), silu_f(s2), silu_f(s3));
    }
    const float4* Wg2 = (const float4*)W2;
#pragma unroll
    for (int i = 0; i < 4; i++) Ws4[tid + 256 * i] = Wg2[tid + 256 * i];
    __syncthreads();

    // ---- stage 2 ----
#pragma unroll
    for (int i = 0; i < 4; i++) { acc[i][0] = 0ull; acc[i][1] = 0ull; }
#pragma unroll 8
    for (int k = 0; k < 64; k++) {
        ulonglong2 w = *(const ulonglong2*)&Ws[k * 64 + tc];
#pragma unroll
        for (int i = 0; i < 4; i++) {
            float a = As[(tr + i) * 64 + k];
            u64 a2 = pack2(a, a);
            fma2(acc[i][0], a2, w.x);
            fma2(acc[i][1], a2, w.y);
        }
    }
    float4* Og = (float4*)(g_cst2 + (size_t)blockIdx.x * 4096);
#pragma unroll
    for (int i = 0; i < 4; i++) {
        float s0, s1, s2, s3;
        unpack2(acc[i][0], s0, s1); unpack2(acc[i][1], s2, s3);
        Og[((tr + i) * 64 + tc) >> 2] =
            make_float4(silu_f(s0), silu_f(s1), silu_f(s2), silu_f(s3));
    }
}

// ---------- K3: triplet kernel (one warp per triplet) ----------
// w = normalize(sum_d rb[e,d]*shb[t,d] * cst2[e,d,:]) * sigmoid(xk[k]); atomic segsum by est
__global__ void __launch_bounds__(256) k_tri(const float* __restrict__ rb,
                                             const float* __restrict__ shb,
                                             const int*   __restrict__ tri_k,
                                             const int*   __restrict__ eks,
                                             const int*   __restrict__ est) {
    int t = (blockIdx.x * blockDim.x + threadIdx.x) >> 5;
    int lane = threadIdx.x & 31;
    if (t >= N_TRI) return;
    int e = eks[t], knode = tri_k[t], eo = est[t];

    float cl = (lane < NORB) ? rb[(size_t)e * NORB + lane] * shb[(size_t)t * NORB + lane] : 0.f;

    const u64* C = (const u64*)(g_cst2 + (size_t)e * (NORB * CONV));
    u64 acc = 0ull;
#pragma unroll
    for (int d = 0; d < NORB; d++) {
        float c = __shfl_sync(0xffffffffu, cl, d);
        fma2(acc, pack2(c, c), C[d * 32 + lane]);
    }
    float a0, a1; unpack2(acc, a0, a1);
    float ss = a0 * a0 + a1 * a1;
#pragma unroll
    for (int o = 16; o; o >>= 1) ss += __shfl_xor_sync(0xffffffffu, ss, o);
    float inv = 1.f / fmaxf(sqrtf(ss), 1e-12f);

    float2 sg = *(const float2*)(g_xksig + (size_t)knode * CONV + 2 * lane);
    atomicAdd(&g_tbw[(size_t)eo * CONV + 2 * lane    ], a0 * inv * sg.x);
    atomicAdd(&g_tbw[(size_t)eo * CONV + 2 * lane + 1], a1 * inv * sg.y);
}

// ---------- K4: fused edge kernel (one warp per edge, weights in smem) ----------
#define SMEM_EDGE_FLOATS (4096 /*W3*/ + 4096 /*Wb*/ + 8192 /*Wn1*/ + 4096 /*Wn2*/ + 64 + 64 + 8 * 320)
__global__ void __launch_bounds__(256) k_edge(const float* __restrict__ rb,
                                              const int*   __restrict__ idx_s,
                                              const int*   __restrict__ idx_t,
                                              const float* __restrict__ W3g,
                                              const float* __restrict__ Wbg,
                                              const float* __restrict__ Wn1g,
                                              const float* __restrict__ bn1g,
                                              const float* __restrict__ Wn2g,
                                              const float* __restrict__ bn2g) {
    extern __shared__ __align__(16) float sm[];
    float* w3  = sm;
    float* wb  = w3  + 4096;
    float* wn1 = wb  + 4096;
    float* wn2 = wn1 + 8192;
    float* b1s = wn2 + 4096;
    float* b2s = b1s + 64;
    float* scr = b2s + 64;
    int tid = threadIdx.x;
    for (int i = tid; i < 4096; i += 256) { w3[i] = W3g[i]; wb[i] = Wbg[i]; wn2[i] = Wn2g[i]; }
    for (int i = tid; i < 8192; i += 256) wn1[i] = Wn1g[i];
    if (tid < 64) { b1s[tid] = bn1g[tid]; b2s[tid] = bn2g[tid]; }
    __syncthreads();

    int wid = tid >> 5, lane = tid & 31;
    float* tw  = scr + wid * 320;     // 64
    float* cat = tw + 64;             // 128
    float* nf  = cat + 128;           // 64
    float* lc  = nf + 64;             // 64
    const int j0 = 2 * lane;

    for (int e = blockIdx.x * 8 + wid; e < N_EDGES; e += gridDim.x * 8) {
        // three-body weight row -> smem
        float2 twv = *(const float2*)(g_tbw + (size_t)e * CONV + j0);
        tw[j0] = twv.x; tw[j0 + 1] = twv.y;

        // lcao_sum = sum_d rb[e,d] * cst2[e,d,:]
        float cl = (lane < NORB) ? rb[(size_t)e * NORB + lane] : 0.f;
        const u64* C = (const u64*)(g_cst2 + (size_t)e * (NORB * CONV));
        u64 ls = 0ull;
#pragma unroll
        for (int d = 0; d < NORB; d++) {
            float c = __shfl_sync(0xffffffffu, cl, d);
            fma2(ls, pack2(c, c), C[d * 32 + lane]);
        }
        __syncwarp();

        // proj = tw @ W_three
        u64 p = 0ull;
#pragma unroll 8
        for (int k = 0; k < 64; k++) {
            float tk = tw[k];
            fma2(p, pack2(tk, tk), *(const u64*)(w3 + k * 64 + j0));
        }
        float p0, p1, l0, l1;
        unpack2(p, p0, p1);
        unpack2(ls, l0, l1);
        l0 *= (1.f + p0); l1 *= (1.f + p1);
        float ss = l0 * l0 + l1 * l1;
#pragma unroll
        for (int o = 16; o; o >>= 1) ss += __shfl_xor_sync(0xffffffffu, ss, o);
        float inv = 1.f / fmaxf(sqrtf(ss), 1e-12f);
        l0 *= inv; l1 *= inv;
        lc[j0] = l0; lc[j0 + 1] = l1;

        // concat(x1[s], x1[t]) -> smem
        int s = idx_s[e], tt = idx_t[e];
        float2 xa = *(const float2*)(g_x1 + (size_t)s  * CONV + j0);
        float2 xb = *(const float2*)(g_x1 + (size_t)tt * CONV + j0);
        cat[j0] = xa.x; cat[j0 + 1] = xa.y;
        cat[64 + j0] = xb.x; cat[64 + j0 + 1] = xb.y;
        __syncwarp();

        // n1 = silu(cat @ Wn1 + b1)
        u64 a = pack2(b1s[j0], b1s[j0 + 1]);
#pragma unroll 8
        for (int k = 0; k < 128; k++) {
            float cv = cat[k];
            fma2(a, pack2(cv, cv), *(const u64*)(wn1 + k * 64 + j0));
        }
        float n10, n11; unpack2(a, n10, n11);
        n10 = silu_f(n10); n11 = silu_f(n11);
        nf[j0] = n10; nf[j0 + 1] = n11;
        __syncwarp();

        // n2 = silu(n1 @ Wn2 + b2)
        u64 b = pack2(b2s[j0], b2s[j0 + 1]);
#pragma unroll 8
        for (int k = 0; k < 64; k++) {
            float nv = nf[k];
            fma2(b, pack2(nv, nv), *(const u64*)(wn2 + k * 64 + j0));
        }
        float n20, n21; unpack2(b, n20, n21);
        n20 = silu_f(n20); n21 = silu_f(n21);

        // msg = (lcao @ W_basis) * node_feat; scatter by idx_s
        u64 m = 0ull;
#pragma unroll 8
        for (int k = 0; k < 64; k++) {
            float lv = lc[k];
            fma2(m, pack2(lv, lv), *(const u64*)(wb + k * 64 + j0));
        }
        float m0, m1; unpack2(m, m0, m1);
        atomicAdd(&g_agg[(size_t)s * CONV + j0    ], m0 * n20);
        atomicAdd(&g_agg[(size_t)s * CONV + j0 + 1], m1 * n21);
        __syncwarp();   // protect scr before next iteration
    }
}

// ---------- K5: out = x + agg @ W_out ----------
__global__ void __launch_bounds__(128) k_out(const float* __restrict__ x,
                                             const float* __restrict__ Wout,
                                             float* __restrict__ out) {
    __shared__ float ags[CONV];
    int n = blockIdx.x, j = threadIdx.x;
    if (j < CONV) ags[j] = g_agg[(size_t)n * CONV + j];
    __syncthreads();
    float acc = 0.f;
#pragma unroll 8
    for (int k = 0; k < CONV; k++)
        acc = fmaf(ags[k], Wout[k * EMB + j], acc);
    out[(size_t)n * EMB + j] = x[(size_t)n * EMB + j] + acc;
}

extern "C" void kernel_launch(void* const* d_in, const int* in_sizes, int n_in,
                              void* d_out, int out_size) {
    const float* x      = (const float*)d_in[0];
    const float* cst    = (const float*)d_in[1];
    const float* rb     = (const float*)d_in[2];
    const float* shb    = (const float*)d_in[3];
    const int*   idx_s  = (const int*)  d_in[4];
    const int*   idx_t  = (const int*)  d_in[5];
    const int*   tri_k  = (const int*)  d_in[6];
    const int*   eks    = (const int*)  d_in[7];
    const int*   est    = (const int*)  d_in[8];
    const float* W_node = (const float*)d_in[9];
    const float* b_node = (const float*)d_in[10];
    const float* W_c1   = (const float*)d_in[11];
    const float* W_c2   = (const float*)d_in[12];
    const float* W_three= (const float*)d_in[13];
    const float* W_basis= (const float*)d_in[14];
    const float* W_n1   = (const float*)d_in[15];
    const float* b_n1   = (const float*)d_in[16];
    const float* W_n2   = (const float*)d_in[17];
    const float* b_n2   = (const float*)d_in[18];
    const float* W_out  = (const float*)d_in[19];
    float* out = (float*)d_out;

    const int smem_edge = SMEM_EDGE_FLOATS * (int)sizeof(float);  // 92672 B
    cudaFuncSetAttribute(k_edge, cudaFuncAttributeMaxDynamicSharedMemorySize, smem_edge);

    const int zero_total = N_EDGES * CONV + N_NODES * CONV;
    k_zero<<<(zero_total + 255) / 256, 256>>>();
    k_node<<<N_NODES, 128>>>(x, W_node, b_node);
    k_cst <<<(N_EDGES * NORB) / 64, 256>>>(cst, W_c1, W_c2);
    k_tri <<<(N_TRI * 32) / 256, 256>>>(rb, shb, tri_k, eks, est);
    k_edge<<<1184, 256, smem_edge>>>(rb, idx_s, idx_t, W_three, W_basis,
                                     W_n1, b_n1, W_n2, b_n2);
    k_out <<<N_NODES, 128>>>(x, W_out, out);
}

// round 2
// speedup vs baseline: 1.1535x; 1.1535x over previous
#include <cuda_runtime.h>
#include <cuda_bf16.h>
#include <math.h>

#define N_NODES 20000
#define N_EDGES 100000
#define N_TRI   200000
#define NORB    16
#define EMB     128
#define CONV    64

typedef unsigned long long u64;

// ---------- packed f32x2 helpers (sm_103a FFMA2 path) ----------
__device__ __forceinline__ void fma2(u64 &d, u64 a, u64 b) {
    asm("fma.rn.f32x2 %0, %1, %2, %0;" : "+l"(d) : "l"(a), "l"(b));
}
__device__ __forceinline__ u64 pack2(float lo, float hi) {
    u64 r; asm("mov.b64 %0, {%1, %2};" : "=l"(r) : "f"(lo), "f"(hi)); return r;
}
__device__ __forceinline__ void unpack2(u64 v, float &lo, float &hi) {
    asm("mov.b64 {%0, %1}, %2;" : "=f"(lo), "=f"(hi) : "l"(v));
}
__device__ __forceinline__ float silu_f(float x) { return x / (1.f + __expf(-x)); }
__device__ __forceinline__ float sigmoid_f(float x) { return 1.f / (1.f + __expf(-x)); }
__device__ __forceinline__ void red2(float* p, float a, float b) {
    asm volatile("red.global.add.v2.f32 [%0], {%1, %2};" :: "l"(p), "f"(a), "f"(b) : "memory");
}
__device__ __forceinline__ void red4(float* p, float a, float b, float c, float d) {
    asm volatile("red.global.add.v4.f32 [%0], {%1, %2, %3, %4};"
                 :: "l"(p), "f"(a), "f"(b), "f"(c), "f"(d) : "memory");
}

// ---------- scratch (device globals; no allocation allowed) ----------
__device__ float g_x1   [(size_t)N_NODES * CONV];                 // h[:, :64]
__device__ float g_xksig[(size_t)N_NODES * CONV];                 // sigmoid(h[:, 64:])
__device__ __align__(16) __nv_bfloat16 g_cst2h[(size_t)N_EDGES * NORB * CONV]; // bf16 cst2 (triplet gather)
__device__ float g_lraw [(size_t)N_EDGES * CONV];                 // sum_d rb*cst2 (pre-normalize)
__device__ float g_tbw  [(size_t)N_EDGES * CONV];                 // segment-summed three-body weights
__device__ float g_agg  [(size_t)N_NODES * CONV];                 // segment-summed messages

// ---------- zero the atomic targets ----------
__global__ void k_zero() {
    int i = blockIdx.x * blockDim.x + threadIdx.x;
    const int t1 = N_EDGES * CONV;
    const int total = t1 + N_NODES * CONV;
    if (i < total) {
        if (i < t1) g_tbw[i] = 0.f;
        else        g_agg[i - t1] = 0.f;
    }
}

// ---------- shared 4x4 microtile GEMM (A,W in smem), FFMA2 + float4 A ----------
template<int K, int LDA>
__device__ __forceinline__ void gemm_tile(const float* __restrict__ As,
                                          const float* __restrict__ Ws,
                                          int tr, int tc, u64 acc[4][2]) {
#pragma unroll 4
    for (int k4 = 0; k4 < K / 4; k4++) {
        float4 a[4];
#pragma unroll
        for (int i = 0; i < 4; i++)
            a[i] = *(const float4*)&As[(tr + i) * LDA + k4 * 4];
#pragma unroll
        for (int kk = 0; kk < 4; kk++) {
            ulonglong2 w = *(const ulonglong2*)&Ws[(k4 * 4 + kk) * 64 + tc];
#pragma unroll
            for (int i = 0; i < 4; i++) {
                float x = (kk == 0) ? a[i].x : (kk == 1) ? a[i].y : (kk == 2) ? a[i].z : a[i].w;
                u64 a2 = pack2(x, x);
                fma2(acc[i][0], a2, w.x);
                fma2(acc[i][1], a2, w.y);
            }
        }
    }
}

// ---------- K1: node transform  h = x @ W_node + b ----------
__global__ void __launch_bounds__(128) k_node(const float* __restrict__ x,
                                              const float* __restrict__ Wn,
                                              const float* __restrict__ bn) {
    __shared__ float xs[EMB];
    int n = blockIdx.x, j = threadIdx.x;
    xs[j] = x[(size_t)n * EMB + j];
    __syncthreads();
    float acc = bn[j];
#pragma unroll 8
    for (int k = 0; k < EMB; k++)
        acc = fmaf(xs[k], Wn[k * EMB + j], acc);
    if (j < CONV) g_x1[(size_t)n * CONV + j] = acc;
    else          g_xksig[(size_t)n * CONV + (j - CONV)] = sigmoid_f(acc);
}

// ---------- K2: cst2 = silu(silu(cst@W1)@W2); write bf16 copy + per-edge lraw ----------
// Block = 64 rows = exactly 4 edges (16 orbitals each). 256 threads, 4x4 microtiles.
__global__ void __launch_bounds__(256) k_cst(const float* __restrict__ A,
                                             const float* __restrict__ W1,
                                             const float* __restrict__ W2,
                                             const float* __restrict__ rb) {
    __shared__ __align__(16) float Ws[4096];
    __shared__ __align__(16) float As[4096];
    int tid = threadIdx.x;
    int wid = tid >> 5, lane = tid & 31;
    float4* Ws4 = (float4*)Ws;
    float4* As4 = (float4*)As;
    const float4* Wg1 = (const float4*)W1;
    const float4* Ag  = (const float4*)(A + (size_t)blockIdx.x * 4096);
#pragma unroll
    for (int i = 0; i < 4; i++) {
        Ws4[tid + 256 * i] = Wg1[tid + 256 * i];
        As4[tid + 256 * i] = Ag [tid + 256 * i];
    }
    __syncthreads();

    const int tr = (tid >> 4) << 2;
    const int tc = (tid & 15) << 2;
    u64 acc[4][2];

    // ---- stage 1 ----
#pragma unroll
    for (int i = 0; i < 4; i++) { acc[i][0] = 0ull; acc[i][1] = 0ull; }
    gemm_tile<64, 64>(As, Ws, tr, tc, acc);
    __syncthreads();
#pragma unroll
    for (int i = 0; i < 4; i++) {
        float s0, s1, s2, s3;
        unpack2(acc[i][0], s0, s1); unpack2(acc[i][1], s2, s3);
        As4[((tr + i) * 64 + tc) >> 2] =
            make_float4(silu_f(s0), silu_f(s1), silu_f(s2), silu_f(s3));
    }
    const float4* Wg2 = (const float4*)W2;
#pragma unroll
    for (int i = 0; i < 4; i++) Ws4[tid + 256 * i] = Wg2[tid + 256 * i];
    __syncthreads();

    // ---- stage 2 ----
#pragma unroll
    for (int i = 0; i < 4; i++) { acc[i][0] = 0ull; acc[i][1] = 0ull; }
    gemm_tile<64, 64>(As, Ws, tr, tc, acc);
    __syncthreads();   // everyone done reading As before overwrite
#pragma unroll
    for (int i = 0; i < 4; i++) {
        float s0, s1, s2, s3;
        unpack2(acc[i][0], s0, s1); unpack2(acc[i][1], s2, s3);
        As4[((tr + i) * 64 + tc) >> 2] =
            make_float4(silu_f(s0), silu_f(s1), silu_f(s2), silu_f(s3));
    }
    __syncthreads();

    // ---- bf16 store of cst2 ----
    const size_t ebase = (size_t)blockIdx.x * 4096;
#pragma unroll
    for (int i = 0; i < 4; i++) {
        float4 v = As4[tid + 256 * i];
        __nv_bfloat162 lo = __float22bfloat162_rn(make_float2(v.x, v.y));
        __nv_bfloat162 hi = __float22bfloat162_rn(make_float2(v.z, v.w));
        uint2 st;
        st.x = *reinterpret_cast<unsigned*>(&lo);
        st.y = *reinterpret_cast<unsigned*>(&hi);
        *reinterpret_cast<uint2*>(g_cst2h + ebase + (size_t)(tid + 256 * i) * 4) = st;
    }

    // ---- lraw: per-edge sum_d rb[e,d] * cst2[e,d,:] from smem (warps 0-3) ----
    if (wid < 4) {
        int e = blockIdx.x * 4 + wid;
        float coef = (lane < NORB) ? rb[(size_t)e * NORB + lane] : 0.f;
        float ax = 0.f, ay = 0.f;
#pragma unroll
        for (int d = 0; d < NORB; d++) {
            float c = __shfl_sync(0xffffffffu, coef, d);
            float2 v = *(const float2*)&As[(wid * 16 + d) * 64 + 2 * lane];
            ax = fmaf(c, v.x, ax);
            ay = fmaf(c, v.y, ay);
        }
        *(float2*)&g_lraw[(size_t)e * CONV + 2 * lane] = make_float2(ax, ay);
    }
}

// ---------- K3: triplet kernel (one warp per triplet, bf16 gather) ----------
__global__ void __launch_bounds__(256) k_tri(const float* __restrict__ rb,
                                             const float* __restrict__ shb,
                                             const int*   __restrict__ tri_k,
                                             const int*   __restrict__ eks,
                                             const int*   __restrict__ est) {
    int t = (blockIdx.x * blockDim.x + threadIdx.x) >> 5;
    int lane = threadIdx.x & 31;
    if (t >= N_TRI) return;
    int e = eks[t], knode = tri_k[t], eo = est[t];

    float cl = (lane < NORB) ? rb[(size_t)e * NORB + lane] * shb[(size_t)t * NORB + lane] : 0.f;

    const __nv_bfloat162* C = (const __nv_bfloat162*)(g_cst2h + (size_t)e * (NORB * CONV));
    float a0 = 0.f, a1 = 0.f;
#pragma unroll
    for (int d = 0; d < NORB; d++) {
        float c = __shfl_sync(0xffffffffu, cl, d);
        float2 v = __bfloat1622float2(C[d * 32 + lane]);
        a0 = fmaf(c, v.x, a0);
        a1 = fmaf(c, v.y, a1);
    }
    float ss = a0 * a0 + a1 * a1;
#pragma unroll
    for (int o = 16; o; o >>= 1) ss += __shfl_xor_sync(0xffffffffu, ss, o);
    float inv = 1.f / fmaxf(sqrtf(ss), 1e-12f);

    float2 sg = *(const float2*)(g_xksig + (size_t)knode * CONV + 2 * lane);
    red2(&g_tbw[(size_t)eo * CONV + 2 * lane], a0 * inv * sg.x, a1 * inv * sg.y);
}

// ---------- K4: block-tiled edge kernel: 64 edges/block, weights in smem once ----------
// smem floats: w3 4096 | wb 4096 | wn2 4096 | wn1 8192 | b1 64 | b2 64 | buf1 4096 | buf2 8192 | buf3 4096
#define EDGE_SMEM_FLOATS (4096*3 + 8192 + 128 + 4096 + 8192 + 4096)
#define EDGE_SMEM_BYTES  (EDGE_SMEM_FLOATS * 4 + 128 * 4)
__global__ void __launch_bounds__(256) k_edge(const int* __restrict__ idx_s,
                                              const int* __restrict__ idx_t,
                                              const float* __restrict__ W3g,
                                              const float* __restrict__ Wbg,
                                              const float* __restrict__ Wn1g,
                                              const float* __restrict__ bn1g,
                                              const float* __restrict__ Wn2g,
                                              const float* __restrict__ bn2g) {
    extern __shared__ __align__(16) float sm[];
    float* w3  = sm;              // 4096
    float* wb  = w3  + 4096;      // 4096
    float* wn2 = wb  + 4096;      // 4096
    float* wn1 = wn2 + 4096;      // 8192
    float* b1s = wn1 + 8192;      // 64
    float* b2s = b1s + 64;        // 64
    float* buf1 = b2s + 64;       // 4096  (tw -> nf)
    float* buf2 = buf1 + 4096;    // 8192  (cat)
    float* buf3 = buf2 + 8192;    // 4096  (lraw -> lc)
    int*   es   = (int*)(buf3 + 4096);  // 64
    int*   et   = es + 64;              // 64

    const int tid = threadIdx.x;
    // weights -> smem (once per block)
    for (int i = tid; i < 1024; i += 256) {
        ((float4*)w3 )[i] = ((const float4*)W3g )[i];
        ((float4*)wb )[i] = ((const float4*)Wbg )[i];
        ((float4*)wn2)[i] = ((const float4*)Wn2g)[i];
    }
    for (int i = tid; i < 2048; i += 256)
        ((float4*)wn1)[i] = ((const float4*)Wn1g)[i];
    if (tid < 64) { b1s[tid] = bn1g[tid]; b2s[tid] = bn2g[tid]; }

    const int e0 = blockIdx.x * 64;
    if (tid < 64) {
        int e = e0 + tid;
        es[tid] = (e < N_EDGES) ? idx_s[e] : 0;
        et[tid] = (e < N_EDGES) ? idx_t[e] : 0;
    }
    const float4 z4 = make_float4(0.f, 0.f, 0.f, 0.f);
    // tw + lraw tiles
    for (int i = tid; i < 1024; i += 256) {
        int r = i >> 4, e = e0 + r;
        bool ok = (e < N_EDGES);
        ((float4*)buf1)[i] = ok ? ((const float4*)g_tbw )[(size_t)e * 16 + (i & 15)] : z4;
        ((float4*)buf3)[i] = ok ? ((const float4*)g_lraw)[(size_t)e * 16 + (i & 15)] : z4;
    }
    __syncthreads();

    // cat gather (issued early; consumed after next sync)
    for (int i = tid; i < 2048; i += 256) {
        int r = i >> 5, c4 = i & 31;
        int node = (c4 < 16) ? es[r] : et[r];
        int cc   = (c4 < 16) ? c4 : c4 - 16;
        ((float4*)buf2)[i] = (e0 + r < N_EDGES)
            ? ((const float4*)g_x1)[(size_t)node * 16 + cc] : z4;
    }

    const int tr = (tid >> 4) << 2;
    const int tc = (tid & 15) << 2;
    u64 acc[4][2];

    // ---- proj = tw @ W_three ----
#pragma unroll
    for (int i = 0; i < 4; i++) { acc[i][0] = 0ull; acc[i][1] = 0ull; }
    gemm_tile<64, 64>(buf1, w3, tr, tc, acc);

    // ---- lc = normalize(lraw * (1 + proj)) per edge row ----
    float l[4][4], ssq[4];
#pragma unroll
    for (int i = 0; i < 4; i++) {
        float p0, p1, p2, p3;
        unpack2(acc[i][0], p0, p1); unpack2(acc[i][1], p2, p3);
        float4 lr = *(const float4*)&buf3[(tr + i) * 64 + tc];
        l[i][0] = lr.x * (1.f + p0);
        l[i][1] = lr.y * (1.f + p1);
        l[i][2] = lr.z * (1.f + p2);
        l[i][3] = lr.w * (1.f + p3);
        ssq[i] = l[i][0]*l[i][0] + l[i][1]*l[i][1] + l[i][2]*l[i][2] + l[i][3]*l[i][3];
    }
#pragma unroll
    for (int m = 1; m < 16; m <<= 1) {
#pragma unroll
        for (int i = 0; i < 4; i++)
            ssq[i] += __shfl_xor_sync(0xffffffffu, ssq[i], m);
    }
#pragma unroll
    for (int i = 0; i < 4; i++) {
        float inv = 1.f / fmaxf(sqrtf(ssq[i]), 1e-12f);
        *(float4*)&buf3[(tr + i) * 64 + tc] =
            make_float4(l[i][0]*inv, l[i][1]*inv, l[i][2]*inv, l[i][3]*inv);
    }
    __syncthreads();   // buf2 (cat) ready; buf3 (lc) complete; buf1 free

    // ---- n1 = silu(cat @ Wn1 + b1) -> buf1 ----
    {
        u64 bias0 = pack2(b1s[tc], b1s[tc + 1]);
        u64 bias1 = pack2(b1s[tc + 2], b1s[tc + 3]);
#pragma unroll
        for (int i = 0; i < 4; i++) { acc[i][0] = bias0; acc[i][1] = bias1; }
    }
    gemm_tile<128, 128>(buf2, wn1, tr, tc, acc);
#pragma unroll
    for (int i = 0; i < 4; i++) {
        float s0, s1, s2, s3;
        unpack2(acc[i][0], s0, s1); unpack2(acc[i][1], s2, s3);
        *(float4*)&buf1[(tr + i) * 64 + tc] =
            make_float4(silu_f(s0), silu_f(s1), silu_f(s2), silu_f(s3));
    }
    __syncthreads();

    // ---- n2 = silu(n1 @ Wn2 + b2) -> regs ----
    float nf[4][4];
    {
        u64 bias0 = pack2(b2s[tc], b2s[tc + 1]);
        u64 bias1 = pack2(b2s[tc + 2], b2s[tc + 3]);
#pragma unroll
        for (int i = 0; i < 4; i++) { acc[i][0] = bias0; acc[i][1] = bias1; }
    }
    gemm_tile<64, 64>(buf1, wn2, tr, tc, acc);
#pragma unroll
    for (int i = 0; i < 4; i++) {
        float s0, s1, s2, s3;
        unpack2(acc[i][0], s0, s1); unpack2(acc[i][1], s2, s3);
        nf[i][0] = silu_f(s0); nf[i][1] = silu_f(s1);
        nf[i][2] = silu_f(s2); nf[i][3] = silu_f(s3);
    }

    // ---- m = lc @ W_basis; msg = m * nf; scatter by idx_s ----
#pragma unroll
    for (int i = 0; i < 4; i++) { acc[i][0] = 0ull; acc[i][1] = 0ull; }
    gemm_tile<64, 64>(buf3, wb, tr, tc, acc);
#pragma unroll
    for (int i = 0; i < 4; i++) {
        int e = e0 + tr + i;
        if (e < N_EDGES) {
            float m0, m1, m2, m3;
            unpack2(acc[i][0], m0, m1); unpack2(acc[i][1], m2, m3);
            red4(&g_agg[(size_t)es[tr + i] * CONV + tc],
                 m0 * nf[i][0], m1 * nf[i][1], m2 * nf[i][2], m3 * nf[i][3]);
        }
    }
}

// ---------- K5: out = x + agg @ W_out ----------
__global__ void __launch_bounds__(128) k_out(const float* __restrict__ x,
                                             const float* __restrict__ Wout,
                                             float* __restrict__ out) {
    __shared__ float ags[CONV];
    int n = blockIdx.x, j = threadIdx.x;
    if (j < CONV) ags[j] = g_agg[(size_t)n * CONV + j];
    __syncthreads();
    float acc = 0.f;
#pragma unroll 8
    for (int k = 0; k < CONV; k++)
        acc = fmaf(ags[k], Wout[k * EMB + j], acc);
    out[(size_t)n * EMB + j] = x[(size_t)n * EMB + j] + acc;
}

extern "C" void kernel_launch(void* const* d_in, const int* in_sizes, int n_in,
                              void* d_out, int out_size) {
    const float* x      = (const float*)d_in[0];
    const float* cst    = (const float*)d_in[1];
    const float* rb     = (const float*)d_in[2];
    const float* shb    = (const float*)d_in[3];
    const int*   idx_s  = (const int*)  d_in[4];
    const int*   idx_t  = (const int*)  d_in[5];
    const int*   tri_k  = (const int*)  d_in[6];
    const int*   eks    = (const int*)  d_in[7];
    const int*   est    = (const int*)  d_in[8];
    const float* W_node = (const float*)d_in[9];
    const float* b_node = (const float*)d_in[10];
    const float* W_c1   = (const float*)d_in[11];
    const float* W_c2   = (const float*)d_in[12];
    const float* W_three= (const float*)d_in[13];
    const float* W_basis= (const float*)d_in[14];
    const float* W_n1   = (const float*)d_in[15];
    const float* b_n1   = (const float*)d_in[16];
    const float* W_n2   = (const float*)d_in[17];
    const float* b_n2   = (const float*)d_in[18];
    const float* W_out  = (const float*)d_in[19];
    float* out = (float*)d_out;

    cudaFuncSetAttribute(k_edge, cudaFuncAttributeMaxDynamicSharedMemorySize, EDGE_SMEM_BYTES);

    const int zero_total = N_EDGES * CONV + N_NODES * CONV;
    k_zero<<<(zero_total + 255) / 256, 256>>>();
    k_node<<<N_NODES, 128>>>(x, W_node, b_node);
    k_cst <<<(N_EDGES * NORB) / 64, 256>>>(cst, W_c1, W_c2, rb);
    k_tri <<<(N_TRI * 32) / 256, 256>>>(rb, shb, tri_k, eks, est);
    k_edge<<<(N_EDGES + 63) / 64, 256, EDGE_SMEM_BYTES>>>(idx_s, idx_t, W_three, W_basis,
                                                          W_n1, b_n1, W_n2, b_n2);
    k_out <<<N_NODES, 128>>>(x, W_out, out);
}

// round 4
// speedup vs baseline: 1.2860x; 1.1149x over previous
#include <cuda_runtime.h>
#include <cuda_bf16.h>
#include <math.h>
#include <stdint.h>

#define N_NODES 20000
#define N_EDGES 100000
#define N_TRI   200000
#define NORB    16
#define EMB     128
#define CONV    64

typedef unsigned long long u64;

// ---------- packed f32x2 helpers ----------
__device__ __forceinline__ void fma2(u64 &d, u64 a, u64 b) {
    asm("fma.rn.f32x2 %0, %1, %2, %0;" : "+l"(d) : "l"(a), "l"(b));
}
__device__ __forceinline__ u64 pack2(float lo, float hi) {
    u64 r; asm("mov.b64 %0, {%1, %2};" : "=l"(r) : "f"(lo), "f"(hi)); return r;
}
__device__ __forceinline__ void unpack2(u64 v, float &lo, float &hi) {
    asm("mov.b64 {%0, %1}, %2;" : "=f"(lo), "=f"(hi) : "l"(v));
}
__device__ __forceinline__ float silu_f(float x) { return x / (1.f + __expf(-x)); }
__device__ __forceinline__ float sigmoid_f(float x) { return 1.f / (1.f + __expf(-x)); }
__device__ __forceinline__ void red2(float* p, float a, float b) {
    asm volatile("red.global.add.v2.f32 [%0], {%1, %2};" :: "l"(p), "f"(a), "f"(b) : "memory");
}
__device__ __forceinline__ void red4(float* p, float a, float b, float c, float d) {
    asm volatile("red.global.add.v4.f32 [%0], {%1, %2, %3, %4};"
                 :: "l"(p), "f"(a), "f"(b), "f"(c), "f"(d) : "memory");
}
__device__ __forceinline__ uint32_t f2tf32(float x) {
    uint32_t r; asm("cvt.rna.tf32.f32 %0, %1;" : "=r"(r) : "f"(x)); return r;
}
// tf32 m16n8k8 mma (portable sm_80+ path -> HMMA on tensor pipe)
__device__ __forceinline__ void mma_tf32(float d[4], const uint32_t a[4],
                                         uint32_t b0, uint32_t b1) {
    asm("mma.sync.aligned.m16n8k8.row.col.f32.tf32.tf32.f32 "
        "{%0,%1,%2,%3}, {%4,%5,%6,%7}, {%8,%9}, {%0,%1,%2,%3};"
        : "+f"(d[0]), "+f"(d[1]), "+f"(d[2]), "+f"(d[3])
        : "r"(a[0]), "r"(a[1]), "r"(a[2]), "r"(a[3]), "r"(b0), "r"(b1));
}

// ---------- scratch ----------
__device__ float g_x1   [(size_t)N_NODES * CONV];
__device__ float g_xksig[(size_t)N_NODES * CONV];
__device__ __align__(16) __nv_bfloat16 g_cst2h[(size_t)N_EDGES * NORB * CONV];
__device__ float g_lraw [(size_t)N_EDGES * CONV];
__device__ float g_tbw  [(size_t)N_EDGES * CONV];
__device__ float g_agg  [(size_t)N_NODES * CONV];
__device__ __align__(16) uint32_t g_w1t[4096];   // W1^T, tf32 bits, [n][k]
__device__ __align__(16) uint32_t g_w2t[4096];   // W2^T, tf32 bits, [n][k]

// ---------- zero atomic targets ----------
__global__ void k_zero() {
    int i = blockIdx.x * blockDim.x + threadIdx.x;
    const int t1 = N_EDGES * CONV;
    const int total = t1 + N_NODES * CONV;
    if (i < total) {
        if (i < t1) g_tbw[i] = 0.f;
        else        g_agg[i - t1] = 0.f;
    }
}

// ---------- prep: W (in,out) -> W^T [n][k] tf32 bits ----------
__global__ void k_prepw(const float* __restrict__ W1, const float* __restrict__ W2) {
    for (int i = threadIdx.x; i < 4096; i += 256) {
        int n = i >> 6, k = i & 63;      // dst [n][k] <- src [k][n]
        g_w1t[i] = f2tf32(W1[k * 64 + n]);
        g_w2t[i] = f2tf32(W2[k * 64 + n]);
    }
}

// ---------- K1: node transform ----------
__global__ void __launch_bounds__(128) k_node(const float* __restrict__ x,
                                              const float* __restrict__ Wn,
                                              const float* __restrict__ bn) {
    __shared__ float xs[EMB];
    int n = blockIdx.x, j = threadIdx.x;
    xs[j] = x[(size_t)n * EMB + j];
    __syncthreads();
    float acc = bn[j];
#pragma unroll 8
    for (int k = 0; k < EMB; k++)
        acc = fmaf(xs[k], Wn[k * EMB + j], acc);
    if (j < CONV) g_x1[(size_t)n * CONV + j] = acc;
    else          g_xksig[(size_t)n * CONV + (j - CONV)] = sigmoid_f(acc);
}

// ---------- K2: mma.sync tf32 double GEMM ----------
// CTA: 256 rows (16 edges), 8 warps, warp owns 32 rows (2 m16 tiles = 2 edges).
// smem: sA 256x68 fp32(tf32 bits / fp32 in epilogue), sW1/sW2 64x68.
#define LDP 68
#define CST_SMEM_FLOATS (256 * LDP + 2 * 64 * LDP)
#define CST_SMEM_BYTES  (CST_SMEM_FLOATS * 4)
__global__ void __launch_bounds__(256, 2) k_cst_mma(const float* __restrict__ A,
                                                    const float* __restrict__ rb) {
    extern __shared__ __align__(16) float sm[];
    float*    sA  = sm;                  // 256*68
    uint32_t* sW1 = (uint32_t*)(sm + 256 * LDP);
    uint32_t* sW2 = sW1 + 64 * LDP;
    uint32_t* sAu = (uint32_t*)sA;

    const int tid = threadIdx.x, wid = tid >> 5, lane = tid & 31;
    const int g = lane >> 2, tg = lane & 3;

    // weights -> smem [n][k] stride 68
    for (int i = tid; i < 4096; i += 256) {
        int n = i >> 6, k = i & 63;
        sW1[n * LDP + k] = g_w1t[i];
        sW2[n * LDP + k] = g_w2t[i];
    }
    // A tile -> smem (cvt to tf32 bits), stride 68
    const float4* Ag = (const float4*)(A + (size_t)blockIdx.x * (256 * 64));
    for (int i = tid; i < 4096; i += 256) {
        int r = i >> 4, c4 = i & 15;
        float4 v = Ag[i];
        uint32_t* dst = sAu + r * LDP + c4 * 4;
        dst[0] = f2tf32(v.x); dst[1] = f2tf32(v.y);
        dst[2] = f2tf32(v.z); dst[3] = f2tf32(v.w);
    }
    __syncthreads();

    float acc[2][8][4];
    uint32_t a[2][4];
    const int wr0 = wid * 32;

    // ================= stage 1: Y = A @ W1 =================
#pragma unroll
    for (int t = 0; t < 2; t++)
#pragma unroll
        for (int at = 0; at < 8; at++)
#pragma unroll
            for (int q = 0; q < 4; q++) acc[t][at][q] = 0.f;

#pragma unroll
    for (int ks = 0; ks < 8; ks++) {
        const int kb = ks * 8;
#pragma unroll
        for (int t = 0; t < 2; t++) {
            int r = wr0 + t * 16 + g;
            a[t][0] = sAu[r * LDP + kb + tg];
            a[t][1] = sAu[(r + 8) * LDP + kb + tg];
            a[t][2] = sAu[r * LDP + kb + tg + 4];
            a[t][3] = sAu[(r + 8) * LDP + kb + tg + 4];
        }
#pragma unroll
        for (int at = 0; at < 8; at++) {
            uint32_t b0 = sW1[(at * 8 + g) * LDP + kb + tg];
            uint32_t b1 = sW1[(at * 8 + g) * LDP + kb + tg + 4];
            mma_tf32(acc[0][at], a[0], b0, b1);
            mma_tf32(acc[1][at], a[1], b0, b1);
        }
    }
    // silu -> tf32 -> back into sA (warp-private rows: no CTA sync needed)
#pragma unroll
    for (int t = 0; t < 2; t++) {
        int r = wr0 + t * 16 + g;
#pragma unroll
        for (int at = 0; at < 8; at++) {
            int c = at * 8 + 2 * tg;
            sAu[r * LDP + c]           = f2tf32(silu_f(acc[t][at][0]));
            sAu[r * LDP + c + 1]       = f2tf32(silu_f(acc[t][at][1]));
            sAu[(r + 8) * LDP + c]     = f2tf32(silu_f(acc[t][at][2]));
            sAu[(r + 8) * LDP + c + 1] = f2tf32(silu_f(acc[t][at][3]));
        }
    }
    __syncwarp();

    // ================= stage 2: Z = silu(Y) @ W2 =================
#pragma unroll
    for (int t = 0; t < 2; t++)
#pragma unroll
        for (int at = 0; at < 8; at++)
#pragma unroll
            for (int q = 0; q < 4; q++) acc[t][at][q] = 0.f;

#pragma unroll
    for (int ks = 0; ks < 8; ks++) {
        const int kb = ks * 8;
#pragma unroll
        for (int t = 0; t < 2; t++) {
            int r = wr0 + t * 16 + g;
            a[t][0] = sAu[r * LDP + kb + tg];
            a[t][1] = sAu[(r + 8) * LDP + kb + tg];
            a[t][2] = sAu[r * LDP + kb + tg + 4];
            a[t][3] = sAu[(r + 8) * LDP + kb + tg + 4];
        }
#pragma unroll
        for (int at = 0; at < 8; at++) {
            uint32_t b0 = sW2[(at * 8 + g) * LDP + kb + tg];
            uint32_t b1 = sW2[(at * 8 + g) * LDP + kb + tg + 4];
            mma_tf32(acc[0][at], a[0], b0, b1);
            mma_tf32(acc[1][at], a[1], b0, b1);
        }
    }

    // ========== epilogue: silu, lraw (register shuffles), bf16 store ==========
#pragma unroll
    for (int t = 0; t < 2; t++) {
        const int edge = blockIdx.x * 16 + wid * 2 + t;
        // rb row for this edge
        float rbl = (lane < NORB) ? rb[(size_t)edge * NORB + lane] : 0.f;
        float rbg  = __shfl_sync(0xffffffffu, rbl, g);
        float rbg8 = __shfl_sync(0xffffffffu, rbl, g + 8);
        int r = wr0 + t * 16 + g;
#pragma unroll
        for (int at = 0; at < 8; at++) {
            float v0 = silu_f(acc[t][at][0]);
            float v1 = silu_f(acc[t][at][1]);
            float v2 = silu_f(acc[t][at][2]);
            float v3 = silu_f(acc[t][at][3]);
            int c = at * 8 + 2 * tg;
            // fp32 silu values into sA (warp-private rows) for coalesced bf16 store
            sA[r * LDP + c]           = v0;
            sA[r * LDP + c + 1]       = v1;
            sA[(r + 8) * LDP + c]     = v2;
            sA[(r + 8) * LDP + c + 1] = v3;
            // lraw contribution: sum over the 16 orbitals (rows) of this edge
            float c0 = rbg * v0 + rbg8 * v2;
            float c1 = rbg * v1 + rbg8 * v3;
#pragma unroll
            for (int o = 4; o < 32; o <<= 1) {
                c0 += __shfl_xor_sync(0xffffffffu, c0, o);
                c1 += __shfl_xor_sync(0xffffffffu, c1, o);
            }
            if (lane < 4)
                *(float2*)&g_lraw[(size_t)edge * CONV + at * 8 + 2 * tg] =
                    make_float2(c0, c1);
        }
    }
    __syncwarp();

    // bf16 store: each lane writes one of the warp's 32 rows (64 cols)
    {
        int r = wr0 + lane;                       // row within CTA
        size_t grow = (size_t)blockIdx.x * 256 + r;
        uint4* dst = (uint4*)(g_cst2h + grow * 64);
        const float4* src = (const float4*)(sA + r * LDP);
#pragma unroll
        for (int j = 0; j < 8; j++) {
            float4 p = src[2 * j];
            float4 q = src[2 * j + 1];
            __nv_bfloat162 h0 = __float22bfloat162_rn(make_float2(p.x, p.y));
            __nv_bfloat162 h1 = __float22bfloat162_rn(make_float2(p.z, p.w));
            __nv_bfloat162 h2 = __float22bfloat162_rn(make_float2(q.x, q.y));
            __nv_bfloat162 h3 = __float22bfloat162_rn(make_float2(q.z, q.w));
            uint4 u;
            u.x = *reinterpret_cast<unsigned*>(&h0);
            u.y = *reinterpret_cast<unsigned*>(&h1);
            u.z = *reinterpret_cast<unsigned*>(&h2);
            u.w = *reinterpret_cast<unsigned*>(&h3);
            dst[j] = u;
        }
    }
}

// ---------- K3: triplet kernel ----------
__global__ void __launch_bounds__(256) k_tri(const float* __restrict__ rb,
                                             const float* __restrict__ shb,
                                             const int*   __restrict__ tri_k,
                                             const int*   __restrict__ eks,
                                             const int*   __restrict__ est) {
    int t = (blockIdx.x * blockDim.x + threadIdx.x) >> 5;
    int lane = threadIdx.x & 31;
    if (t >= N_TRI) return;
    int e = eks[t], knode = tri_k[t], eo = est[t];

    float cl = (lane < NORB) ? rb[(size_t)e * NORB + lane] * shb[(size_t)t * NORB + lane] : 0.f;

    const __nv_bfloat162* C = (const __nv_bfloat162*)(g_cst2h + (size_t)e * (NORB * CONV));
    float a0 = 0.f, a1 = 0.f;
#pragma unroll
    for (int d = 0; d < NORB; d++) {
        float c = __shfl_sync(0xffffffffu, cl, d);
        float2 v = __bfloat1622float2(C[d * 32 + lane]);
        a0 = fmaf(c, v.x, a0);
        a1 = fmaf(c, v.y, a1);
    }
    float ss = a0 * a0 + a1 * a1;
#pragma unroll
    for (int o = 16; o; o >>= 1) ss += __shfl_xor_sync(0xffffffffu, ss, o);
    float inv = 1.f / fmaxf(sqrtf(ss), 1e-12f);

    float2 sg = *(const float2*)(g_xksig + (size_t)knode * CONV + 2 * lane);
    red2(&g_tbw[(size_t)eo * CONV + 2 * lane], a0 * inv * sg.x, a1 * inv * sg.y);
}

// ---------- shared 4x4 microtile GEMM for k_edge ----------
template<int K, int LDA>
__device__ __forceinline__ void gemm_tile(const float* __restrict__ As,
                                          const float* __restrict__ Ws,
                                          int tr, int tc, u64 acc[4][2]) {
#pragma unroll 4
    for (int k4 = 0; k4 < K / 4; k4++) {
        float4 a[4];
#pragma unroll
        for (int i = 0; i < 4; i++)
            a[i] = *(const float4*)&As[(tr + i) * LDA + k4 * 4];
#pragma unroll
        for (int kk = 0; kk < 4; kk++) {
            ulonglong2 w = *(const ulonglong2*)&Ws[(k4 * 4 + kk) * 64 + tc];
#pragma unroll
            for (int i = 0; i < 4; i++) {
                float x = (kk == 0) ? a[i].x : (kk == 1) ? a[i].y : (kk == 2) ? a[i].z : a[i].w;
                u64 a2 = pack2(x, x);
                fma2(acc[i][0], a2, w.x);
                fma2(acc[i][1], a2, w.y);
            }
        }
    }
}

// ---------- K4: block-tiled edge kernel ----------
#define EDGE_SMEM_FLOATS (4096*3 + 8192 + 128 + 4096 + 8192 + 4096)
#define EDGE_SMEM_BYTES  (EDGE_SMEM_FLOATS * 4 + 128 * 4)
__global__ void __launch_bounds__(256) k_edge(const int* __restrict__ idx_s,
                                              const int* __restrict__ idx_t,
                                              const float* __restrict__ W3g,
                                              const float* __restrict__ Wbg,
                                              const float* __restrict__ Wn1g,
                                              const float* __restrict__ bn1g,
                                              const float* __restrict__ Wn2g,
                                              const float* __restrict__ bn2g) {
    extern __shared__ __align__(16) float sm[];
    float* w3  = sm;
    float* wb  = w3  + 4096;
    float* wn2 = wb  + 4096;
    float* wn1 = wn2 + 4096;
    float* b1s = wn1 + 8192;
    float* b2s = b1s + 64;
    float* buf1 = b2s + 64;
    float* buf2 = buf1 + 4096;
    float* buf3 = buf2 + 8192;
    int*   es   = (int*)(buf3 + 4096);
    int*   et   = es + 64;

    const int tid = threadIdx.x;
    for (int i = tid; i < 1024; i += 256) {
        ((float4*)w3 )[i] = ((const float4*)W3g )[i];
        ((float4*)wb )[i] = ((const float4*)Wbg )[i];
        ((float4*)wn2)[i] = ((const float4*)Wn2g)[i];
    }
    for (int i = tid; i < 2048; i += 256)
        ((float4*)wn1)[i] = ((const float4*)Wn1g)[i];
    if (tid < 64) { b1s[tid] = bn1g[tid]; b2s[tid] = bn2g[tid]; }

    const int e0 = blockIdx.x * 64;
    if (tid < 64) {
        int e = e0 + tid;
        es[tid] = (e < N_EDGES) ? idx_s[e] : 0;
        et[tid] = (e < N_EDGES) ? idx_t[e] : 0;
    }
    const float4 z4 = make_float4(0.f, 0.f, 0.f, 0.f);
    for (int i = tid; i < 1024; i += 256) {
        int r = i >> 4, e = e0 + r;
        bool ok = (e < N_EDGES);
        ((float4*)buf1)[i] = ok ? ((const float4*)g_tbw )[(size_t)e * 16 + (i & 15)] : z4;
        ((float4*)buf3)[i] = ok ? ((const float4*)g_lraw)[(size_t)e * 16 + (i & 15)] : z4;
    }
    __syncthreads();

    for (int i = tid; i < 2048; i += 256) {
        int r = i >> 5, c4 = i & 31;
        int node = (c4 < 16) ? es[r] : et[r];
        int cc   = (c4 < 16) ? c4 : c4 - 16;
        ((float4*)buf2)[i] = (e0 + r < N_EDGES)
            ? ((const float4*)g_x1)[(size_t)node * 16 + cc] : z4;
    }

    const int tr = (tid >> 4) << 2;
    const int tc = (tid & 15) << 2;
    u64 acc[4][2];

#pragma unroll
    for (int i = 0; i < 4; i++) { acc[i][0] = 0ull; acc[i][1] = 0ull; }
    gemm_tile<64, 64>(buf1, w3, tr, tc, acc);

    float l[4][4], ssq[4];
#pragma unroll
    for (int i = 0; i < 4; i++) {
        float p0, p1, p2, p3;
        unpack2(acc[i][0], p0, p1); unpack2(acc[i][1], p2, p3);
        float4 lr = *(const float4*)&buf3[(tr + i) * 64 + tc];
        l[i][0] = lr.x * (1.f + p0);
        l[i][1] = lr.y * (1.f + p1);
        l[i][2] = lr.z * (1.f + p2);
        l[i][3] = lr.w * (1.f + p3);
        ssq[i] = l[i][0]*l[i][0] + l[i][1]*l[i][1] + l[i][2]*l[i][2] + l[i][3]*l[i][3];
    }
#pragma unroll
    for (int m = 1; m < 16; m <<= 1) {
#pragma unroll
        for (int i = 0; i < 4; i++)
            ssq[i] += __shfl_xor_sync(0xffffffffu, ssq[i], m);
    }
#pragma unroll
    for (int i = 0; i < 4; i++) {
        float inv = 1.f / fmaxf(sqrtf(ssq[i]), 1e-12f);
        *(float4*)&buf3[(tr + i) * 64 + tc] =
            make_float4(l[i][0]*inv, l[i][1]*inv, l[i][2]*inv, l[i][3]*inv);
    }
    __syncthreads();

    {
        u64 bias0 = pack2(b1s[tc], b1s[tc + 1]);
        u64 bias1 = pack2(b1s[tc + 2], b1s[tc + 3]);
#pragma unroll
        for (int i = 0; i < 4; i++) { acc[i][0] = bias0; acc[i][1] = bias1; }
    }
    gemm_tile<128, 128>(buf2, wn1, tr, tc, acc);
#pragma unroll
    for (int i = 0; i < 4; i++) {
        float s0, s1, s2, s3;
        unpack2(acc[i][0], s0, s1); unpack2(acc[i][1], s2, s3);
        *(float4*)&buf1[(tr + i) * 64 + tc] =
            make_float4(silu_f(s0), silu_f(s1), silu_f(s2), silu_f(s3));
    }
    __syncthreads();

    float nf[4][4];
    {
        u64 bias0 = pack2(b2s[tc], b2s[tc + 1]);
        u64 bias1 = pack2(b2s[tc + 2], b2s[tc + 3]);
#pragma unroll
        for (int i = 0; i < 4; i++) { acc[i][0] = bias0; acc[i][1] = bias1; }
    }
    gemm_tile<64, 64>(buf1, wn2, tr, tc, acc);
#pragma unroll
    for (int i = 0; i < 4; i++) {
        float s0, s1, s2, s3;
        unpack2(acc[i][0], s0, s1); unpack2(acc[i][1], s2, s3);
        nf[i][0] = silu_f(s0); nf[i][1] = silu_f(s1);
        nf[i][2] = silu_f(s2); nf[i][3] = silu_f(s3);
    }

#pragma unroll
    for (int i = 0; i < 4; i++) { acc[i][0] = 0ull; acc[i][1] = 0ull; }
    gemm_tile<64, 64>(buf3, wb, tr, tc, acc);
#pragma unroll
    for (int i = 0; i < 4; i++) {
        int e = e0 + tr + i;
        if (e < N_EDGES) {
            float m0, m1, m2, m3;
            unpack2(acc[i][0], m0, m1); unpack2(acc[i][1], m2, m3);
            red4(&g_agg[(size_t)es[tr + i] * CONV + tc],
                 m0 * nf[i][0], m1 * nf[i][1], m2 * nf[i][2], m3 * nf[i][3]);
        }
    }
}

// ---------- K5: out = x + agg @ W_out ----------
__global__ void __launch_bounds__(128) k_out(const float* __restrict__ x,
                                             const float* __restrict__ Wout,
                                             float* __restrict__ out) {
    __shared__ float ags[CONV];
    int n = blockIdx.x, j = threadIdx.x;
    if (j < CONV) ags[j] = g_agg[(size_t)n * CONV + j];
    __syncthreads();
    float acc = 0.f;
#pragma unroll 8
    for (int k = 0; k < CONV; k++)
        acc = fmaf(ags[k], Wout[k * EMB + j], acc);
    out[(size_t)n * EMB + j] = x[(size_t)n * EMB + j] + acc;
}

extern "C" void kernel_launch(void* const* d_in, const int* in_sizes, int n_in,
                              void* d_out, int out_size) {
    const float* x      = (const float*)d_in[0];
    const float* cst    = (const float*)d_in[1];
    const float* rb     = (const float*)d_in[2];
    const float* shb    = (const float*)d_in[3];
    const int*   idx_s  = (const int*)  d_in[4];
    const int*   idx_t  = (const int*)  d_in[5];
    const int*   tri_k  = (const int*)  d_in[6];
    const int*   eks    = (const int*)  d_in[7];
    const int*   est    = (const int*)  d_in[8];
    const float* W_node = (const float*)d_in[9];
    const float* b_node = (const float*)d_in[10];
    const float* W_c1   = (const float*)d_in[11];
    const float* W_c2   = (const float*)d_in[12];
    const float* W_three= (const float*)d_in[13];
    const float* W_basis= (const float*)d_in[14];
    const float* W_n1   = (const float*)d_in[15];
    const float* b_n1   = (const float*)d_in[16];
    const float* W_n2   = (const float*)d_in[17];
    const float* b_n2   = (const float*)d_in[18];
    const float* W_out  = (const float*)d_in[19];
    float* out = (float*)d_out;

    cudaFuncSetAttribute(k_edge,    cudaFuncAttributeMaxDynamicSharedMemorySize, EDGE_SMEM_BYTES);
    cudaFuncSetAttribute(k_cst_mma, cudaFuncAttributeMaxDynamicSharedMemorySize, CST_SMEM_BYTES);

    const int zero_total = N_EDGES * CONV + N_NODES * CONV;
    k_zero<<<(zero_total + 255) / 256, 256>>>();
    k_node<<<N_NODES, 128>>>(x, W_node, b_node);
    k_prepw<<<1, 256>>>(W_c1, W_c2);
    k_cst_mma<<<(N_EDGES * NORB) / 256, 256, CST_SMEM_BYTES>>>(cst, rb);
    k_tri <<<(N_TRI * 32) / 256, 256>>>(rb, shb, tri_k, eks, est);
    k_edge<<<(N_EDGES + 63) / 64, 256, EDGE_SMEM_BYTES>>>(idx_s, idx_t, W_three, W_basis,
                                                          W_n1, b_n1, W_n2, b_n2);
    k_out <<<N_NODES, 128>>>(x, W_out, out);
}

// round 5
// speedup vs baseline: 1.5371x; 1.1953x over previous
#include <cuda_runtime.h>
#include <cuda_bf16.h>
#include <math.h>
#include <stdint.h>

#define N_NODES 20000
#define N_EDGES 100000
#define N_TRI   200000
#define NORB    16
#define EMB     128
#define CONV    64

typedef unsigned long long u64;

// ---------- packed f32x2 helpers ----------
__device__ __forceinline__ void fma2(u64 &d, u64 a, u64 b) {
    asm("fma.rn.f32x2 %0, %1, %2, %0;" : "+l"(d) : "l"(a), "l"(b));
}
__device__ __forceinline__ u64 pack2(float lo, float hi) {
    u64 r; asm("mov.b64 %0, {%1, %2};" : "=l"(r) : "f"(lo), "f"(hi)); return r;
}
__device__ __forceinline__ void unpack2(u64 v, float &lo, float &hi) {
    asm("mov.b64 {%0, %1}, %2;" : "=f"(lo), "=f"(hi) : "l"(v));
}
__device__ __forceinline__ float silu_f(float x) { return x / (1.f + __expf(-x)); }
__device__ __forceinline__ float sigmoid_f(float x) { return 1.f / (1.f + __expf(-x)); }
__device__ __forceinline__ void red2(float* p, float a, float b) {
    asm volatile("red.global.add.v2.f32 [%0], {%1, %2};" :: "l"(p), "f"(a), "f"(b) : "memory");
}
__device__ __forceinline__ void red4(float* p, float a, float b, float c, float d) {
    asm volatile("red.global.add.v4.f32 [%0], {%1, %2, %3, %4};"
                 :: "l"(p), "f"(a), "f"(b), "f"(c), "f"(d) : "memory");
}
__device__ __forceinline__ uint32_t smem_u32(const void* p) {
    uint32_t a;
    asm("{ .reg .u64 t; cvta.to.shared.u64 t, %1; cvt.u32.u64 %0, t; }" : "=r"(a) : "l"(p));
    return a;
}
// portable bf16 m16n8k16 mma -> HMMA on tensor pipe
__device__ __forceinline__ void mma_bf16(float d[4], const uint32_t a[4],
                                         uint32_t b0, uint32_t b1) {
    asm("mma.sync.aligned.m16n8k16.row.col.f32.bf16.bf16.f32 "
        "{%0,%1,%2,%3}, {%4,%5,%6,%7}, {%8,%9}, {%0,%1,%2,%3};"
        : "+f"(d[0]), "+f"(d[1]), "+f"(d[2]), "+f"(d[3])
        : "r"(a[0]), "r"(a[1]), "r"(a[2]), "r"(a[3]), "r"(b0), "r"(b1));
}
__device__ __forceinline__ void ldmx4(uint32_t &r0, uint32_t &r1, uint32_t &r2,
                                      uint32_t &r3, uint32_t addr) {
    asm volatile("ldmatrix.sync.aligned.m8n8.x4.shared.b16 {%0,%1,%2,%3}, [%4];"
                 : "=r"(r0), "=r"(r1), "=r"(r2), "=r"(r3) : "r"(addr));
}
__device__ __forceinline__ unsigned bf2x(float lo, float hi) {
    __nv_bfloat162 h = __float22bfloat162_rn(make_float2(lo, hi));
    return *reinterpret_cast<unsigned*>(&h);
}

// ---------- scratch ----------
__device__ float g_x1   [(size_t)N_NODES * CONV];
__device__ float g_xksig[(size_t)N_NODES * CONV];
__device__ __align__(16) __nv_bfloat16 g_cst2h[(size_t)N_EDGES * NORB * CONV];
__device__ float g_lraw [(size_t)N_EDGES * CONV];
__device__ float g_tbw  [(size_t)N_EDGES * CONV];
__device__ float g_agg  [(size_t)N_NODES * CONV];
__device__ __align__(16) __nv_bfloat16 g_w1h[4096];   // W1^T bf16, [n][k]
__device__ __align__(16) __nv_bfloat16 g_w2h[4096];   // W2^T bf16, [n][k]

// ---------- zero atomic targets ----------
__global__ void k_zero() {
    int i = blockIdx.x * blockDim.x + threadIdx.x;
    const int t1 = N_EDGES * CONV;
    const int total = t1 + N_NODES * CONV;
    if (i < total) {
        if (i < t1) g_tbw[i] = 0.f;
        else        g_agg[i - t1] = 0.f;
    }
}

// ---------- prep: W (in,out) -> W^T [n][k] bf16 ----------
__global__ void k_prepw(const float* __restrict__ W1, const float* __restrict__ W2) {
    for (int i = threadIdx.x; i < 4096; i += 256) {
        int n = i >> 6, k = i & 63;
        g_w1h[i] = __float2bfloat16(W1[k * 64 + n]);
        g_w2h[i] = __float2bfloat16(W2[k * 64 + n]);
    }
}

// ---------- K1: node transform, 4 nodes/block (amortize W reads) ----------
__global__ void __launch_bounds__(128) k_node(const float* __restrict__ x,
                                              const float* __restrict__ Wn,
                                              const float* __restrict__ bn) {
    __shared__ float xs[4][EMB];
    int n0 = blockIdx.x * 4, j = threadIdx.x;
#pragma unroll
    for (int v = 0; v < 4; v++)
        xs[v][j] = x[(size_t)(n0 + v) * EMB + j];
    __syncthreads();
    float a0 = bn[j], a1 = a0, a2 = a0, a3 = a0;
#pragma unroll 4
    for (int k = 0; k < EMB; k++) {
        float w = Wn[k * EMB + j];
        a0 = fmaf(xs[0][k], w, a0);
        a1 = fmaf(xs[1][k], w, a1);
        a2 = fmaf(xs[2][k], w, a2);
        a3 = fmaf(xs[3][k], w, a3);
    }
    if (j < CONV) {
        g_x1[(size_t)(n0 + 0) * CONV + j] = a0;
        g_x1[(size_t)(n0 + 1) * CONV + j] = a1;
        g_x1[(size_t)(n0 + 2) * CONV + j] = a2;
        g_x1[(size_t)(n0 + 3) * CONV + j] = a3;
    } else {
        int jj = j - CONV;
        g_xksig[(size_t)(n0 + 0) * CONV + jj] = sigmoid_f(a0);
        g_xksig[(size_t)(n0 + 1) * CONV + jj] = sigmoid_f(a1);
        g_xksig[(size_t)(n0 + 2) * CONV + jj] = sigmoid_f(a2);
        g_xksig[(size_t)(n0 + 3) * CONV + jj] = sigmoid_f(a3);
    }
}

// ---------- K2: bf16 mma.sync + ldmatrix double GEMM ----------
// CTA: 256 rows (16 edges), 8 warps; warp = 32 rows (2 m16 tiles = 2 edges), N=64, K=64.
#define LDB 72
#define CST_SMEM_BYTES ((256 * LDB + 2 * 64 * LDB) * 2)   // 55296 B
__global__ void __launch_bounds__(256, 2) k_cst_mma(const float* __restrict__ A,
                                                    const float* __restrict__ rb) {
    extern __shared__ __align__(16) __nv_bfloat16 sb[];
    __nv_bfloat16* sA  = sb;                   // 256 x 72
    __nv_bfloat16* sW1 = sb + 256 * LDB;       // 64 x 72
    __nv_bfloat16* sW2 = sW1 + 64 * LDB;
    const uint32_t sAu  = smem_u32(sA);
    const uint32_t sW1u = smem_u32(sW1);
    const uint32_t sW2u = smem_u32(sW2);

    const int tid = threadIdx.x, wid = tid >> 5, lane = tid & 31;
    const int g = lane >> 2, tg = lane & 3;
    const int wr0 = wid * 32;

    // weights -> smem (uint4 = 8 bf16 per copy; dst stride 72, 16B aligned)
    for (int i = tid; i < 512; i += 256) {
        int n = i >> 3, kc = i & 7;
        *(uint4*)(sW1 + n * LDB + kc * 8) = ((const uint4*)g_w1h)[i];
        *(uint4*)(sW2 + n * LDB + kc * 8) = ((const uint4*)g_w2h)[i];
    }
    // A tile -> smem bf16
    const float4* Ag = (const float4*)(A + (size_t)blockIdx.x * (256 * 64));
    for (int i = tid; i < 4096; i += 256) {
        int r = i >> 4, c4 = i & 15;
        float4 v = Ag[i];
        uint2 u = make_uint2(bf2x(v.x, v.y), bf2x(v.z, v.w));
        *(uint2*)(sA + r * LDB + c4 * 4) = u;
    }
    __syncthreads();

    // fragment addresses (byte offsets; bf16 = 2B)
    // A (16x16 tile at row r0, col k0): lanes 0-7 rows 0-7 @k0 | 8-15 rows 8-15 @k0
    //                                   | 16-23 rows 0-7 @k0+8 | 24-31 rows 8-15 @k0+8
    const uint32_t a_off = (uint32_t)((lane & 15) * LDB + ((lane >> 4) << 3)) * 2;
    // B (n-pair at n0, k0): lanes 0-7 n0+l @k0 | 8-15 n0+l @k0+8 | 16-23 n0+8+l @k0 | 24-31 n0+8+l @k0+8
    const uint32_t b_off = (uint32_t)((((lane >> 4) << 3) + (lane & 7)) * LDB +
                                      (((lane >> 3) & 1) << 3)) * 2;

    float acc[2][8][4];
    uint32_t a[2][4];

    // ================= stage 1: Y = A @ W1 =================
#pragma unroll
    for (int t = 0; t < 2; t++)
#pragma unroll
        for (int at = 0; at < 8; at++)
#pragma unroll
            for (int q = 0; q < 4; q++) acc[t][at][q] = 0.f;
#pragma unroll
    for (int ks = 0; ks < 4; ks++) {
        const int k0 = ks * 16;
#pragma unroll
        for (int t = 0; t < 2; t++)
            ldmx4(a[t][0], a[t][1], a[t][2], a[t][3],
                  sAu + a_off + (uint32_t)((wr0 + t * 16) * LDB + k0) * 2);
#pragma unroll
        for (int np = 0; np < 4; np++) {
            uint32_t b0, b1, b2, b3;
            ldmx4(b0, b1, b2, b3, sW1u + b_off + (uint32_t)(np * 16 * LDB + k0) * 2);
            mma_bf16(acc[0][2 * np],     a[0], b0, b1);
            mma_bf16(acc[0][2 * np + 1], a[0], b2, b3);
            mma_bf16(acc[1][2 * np],     a[1], b0, b1);
            mma_bf16(acc[1][2 * np + 1], a[1], b2, b3);
        }
    }
    // silu -> bf16 -> back into sA (warp-private rows)
#pragma unroll
    for (int t = 0; t < 2; t++) {
        int r = wr0 + t * 16 + g;
#pragma unroll
        for (int at = 0; at < 8; at++) {
            int c = at * 8 + 2 * tg;
            *(unsigned*)(sA + r * LDB + c) =
                bf2x(silu_f(acc[t][at][0]), silu_f(acc[t][at][1]));
            *(unsigned*)(sA + (r + 8) * LDB + c) =
                bf2x(silu_f(acc[t][at][2]), silu_f(acc[t][at][3]));
        }
    }
    __syncwarp();

    // ================= stage 2: Z = silu(Y) @ W2 =================
#pragma unroll
    for (int t = 0; t < 2; t++)
#pragma unroll
        for (int at = 0; at < 8; at++)
#pragma unroll
            for (int q = 0; q < 4; q++) acc[t][at][q] = 0.f;
#pragma unroll
    for (int ks = 0; ks < 4; ks++) {
        const int k0 = ks * 16;
#pragma unroll
        for (int t = 0; t < 2; t++)
            ldmx4(a[t][0], a[t][1], a[t][2], a[t][3],
                  sAu + a_off + (uint32_t)((wr0 + t * 16) * LDB + k0) * 2);
#pragma unroll
        for (int np = 0; np < 4; np++) {
            uint32_t b0, b1, b2, b3;
            ldmx4(b0, b1, b2, b3, sW2u + b_off + (uint32_t)(np * 16 * LDB + k0) * 2);
            mma_bf16(acc[0][2 * np],     a[0], b0, b1);
            mma_bf16(acc[0][2 * np + 1], a[0], b2, b3);
            mma_bf16(acc[1][2 * np],     a[1], b0, b1);
            mma_bf16(acc[1][2 * np + 1], a[1], b2, b3);
        }
    }
    __syncwarp();

    // ===== epilogue: silu, lraw (register shuffles), bf16 into sA, coalesced store =====
#pragma unroll
    for (int t = 0; t < 2; t++) {
        const int edge = blockIdx.x * 16 + wid * 2 + t;
        float rbl = (lane < NORB) ? rb[(size_t)edge * NORB + lane] : 0.f;
        float rbg  = __shfl_sync(0xffffffffu, rbl, g);
        float rbg8 = __shfl_sync(0xffffffffu, rbl, g + 8);
        int r = wr0 + t * 16 + g;
#pragma unroll
        for (int at = 0; at < 8; at++) {
            float v0 = silu_f(acc[t][at][0]);
            float v1 = silu_f(acc[t][at][1]);
            float v2 = silu_f(acc[t][at][2]);
            float v3 = silu_f(acc[t][at][3]);
            int c = at * 8 + 2 * tg;
            *(unsigned*)(sA + r * LDB + c)       = bf2x(v0, v1);
            *(unsigned*)(sA + (r + 8) * LDB + c) = bf2x(v2, v3);
            float c0 = rbg * v0 + rbg8 * v2;
            float c1 = rbg * v1 + rbg8 * v3;
#pragma unroll
            for (int o = 4; o < 32; o <<= 1) {
                c0 += __shfl_xor_sync(0xffffffffu, c0, o);
                c1 += __shfl_xor_sync(0xffffffffu, c1, o);
            }
            if (lane < 4)
                *(float2*)&g_lraw[(size_t)edge * CONV + at * 8 + 2 * tg] =
                    make_float2(c0, c1);
        }
    }
    __syncwarp();

    // coalesced bf16 store: lane owns row wr0+lane (128 B = 8 x uint4)
    {
        int r = wr0 + lane;
        size_t grow = (size_t)blockIdx.x * 256 + r;
        uint4* dst = (uint4*)(g_cst2h + grow * 64);
        const __nv_bfloat16* src = sA + r * LDB;
#pragma unroll
        for (int j = 0; j < 8; j++)
            dst[j] = *(const uint4*)(src + j * 8);
    }
}

// ---------- K3: triplet kernel ----------
__global__ void __launch_bounds__(256) k_tri(const float* __restrict__ rb,
                                             const float* __restrict__ shb,
                                             const int*   __restrict__ tri_k,
                                             const int*   __restrict__ eks,
                                             const int*   __restrict__ est) {
    int t = (blockIdx.x * blockDim.x + threadIdx.x) >> 5;
    int lane = threadIdx.x & 31;
    if (t >= N_TRI) return;
    int e = eks[t], knode = tri_k[t], eo = est[t];

    float cl = (lane < NORB) ? rb[(size_t)e * NORB + lane] * shb[(size_t)t * NORB + lane] : 0.f;

    const __nv_bfloat162* C = (const __nv_bfloat162*)(g_cst2h + (size_t)e * (NORB * CONV));
    float a0 = 0.f, a1 = 0.f;
#pragma unroll
    for (int d = 0; d < NORB; d++) {
        float c = __shfl_sync(0xffffffffu, cl, d);
        float2 v = __bfloat1622float2(C[d * 32 + lane]);
        a0 = fmaf(c, v.x, a0);
        a1 = fmaf(c, v.y, a1);
    }
    float ss = a0 * a0 + a1 * a1;
#pragma unroll
    for (int o = 16; o; o >>= 1) ss += __shfl_xor_sync(0xffffffffu, ss, o);
    float inv = 1.f / fmaxf(sqrtf(ss), 1e-12f);

    float2 sg = *(const float2*)(g_xksig + (size_t)knode * CONV + 2 * lane);
    red2(&g_tbw[(size_t)eo * CONV + 2 * lane], a0 * inv * sg.x, a1 * inv * sg.y);
}

// ---------- shared 4x4 microtile GEMM for k_edge ----------
template<int K, int LDA>
__device__ __forceinline__ void gemm_tile(const float* __restrict__ As,
                                          const float* __restrict__ Ws,
                                          int tr, int tc, u64 acc[4][2]) {
#pragma unroll 4
    for (int k4 = 0; k4 < K / 4; k4++) {
        float4 a[4];
#pragma unroll
        for (int i = 0; i < 4; i++)
            a[i] = *(const float4*)&As[(tr + i) * LDA + k4 * 4];
#pragma unroll
        for (int kk = 0; kk < 4; kk++) {
            ulonglong2 w = *(const ulonglong2*)&Ws[(k4 * 4 + kk) * 64 + tc];
#pragma unroll
            for (int i = 0; i < 4; i++) {
                float x = (kk == 0) ? a[i].x : (kk == 1) ? a[i].y : (kk == 2) ? a[i].z : a[i].w;
                u64 a2 = pack2(x, x);
                fma2(acc[i][0], a2, w.x);
                fma2(acc[i][1], a2, w.y);
            }
        }
    }
}

// ---------- K4: block-tiled edge kernel ----------
#define EDGE_SMEM_FLOATS (4096*3 + 8192 + 128 + 4096 + 8192 + 4096)
#define EDGE_SMEM_BYTES  (EDGE_SMEM_FLOATS * 4 + 128 * 4)
__global__ void __launch_bounds__(256) k_edge(const int* __restrict__ idx_s,
                                              const int* __restrict__ idx_t,
                                              const float* __restrict__ W3g,
                                              const float* __restrict__ Wbg,
                                              const float* __restrict__ Wn1g,
                                              const float* __restrict__ bn1g,
                                              const float* __restrict__ Wn2g,
                                              const float* __restrict__ bn2g) {
    extern __shared__ __align__(16) float sm[];
    float* w3  = sm;
    float* wb  = w3  + 4096;
    float* wn2 = wb  + 4096;
    float* wn1 = wn2 + 4096;
    float* b1s = wn1 + 8192;
    float* b2s = b1s + 64;
    float* buf1 = b2s + 64;
    float* buf2 = buf1 + 4096;
    float* buf3 = buf2 + 8192;
    int*   es   = (int*)(buf3 + 4096);
    int*   et   = es + 64;

    const int tid = threadIdx.x;
    for (int i = tid; i < 1024; i += 256) {
        ((float4*)w3 )[i] = ((const float4*)W3g )[i];
        ((float4*)wb )[i] = ((const float4*)Wbg )[i];
        ((float4*)wn2)[i] = ((const float4*)Wn2g)[i];
    }
    for (int i = tid; i < 2048; i += 256)
        ((float4*)wn1)[i] = ((const float4*)Wn1g)[i];
    if (tid < 64) { b1s[tid] = bn1g[tid]; b2s[tid] = bn2g[tid]; }

    const int e0 = blockIdx.x * 64;
    if (tid < 64) {
        int e = e0 + tid;
        es[tid] = (e < N_EDGES) ? idx_s[e] : 0;
        et[tid] = (e < N_EDGES) ? idx_t[e] : 0;
    }
    const float4 z4 = make_float4(0.f, 0.f, 0.f, 0.f);
    for (int i = tid; i < 1024; i += 256) {
        int r = i >> 4, e = e0 + r;
        bool ok = (e < N_EDGES);
        ((float4*)buf1)[i] = ok ? ((const float4*)g_tbw )[(size_t)e * 16 + (i & 15)] : z4;
        ((float4*)buf3)[i] = ok ? ((const float4*)g_lraw)[(size_t)e * 16 + (i & 15)] : z4;
    }
    __syncthreads();

    for (int i = tid; i < 2048; i += 256) {
        int r = i >> 5, c4 = i & 31;
        int node = (c4 < 16) ? es[r] : et[r];
        int cc   = (c4 < 16) ? c4 : c4 - 16;
        ((float4*)buf2)[i] = (e0 + r < N_EDGES)
            ? ((const float4*)g_x1)[(size_t)node * 16 + cc] : z4;
    }

    const int tr = (tid >> 4) << 2;
    const int tc = (tid & 15) << 2;
    u64 acc[4][2];

#pragma unroll
    for (int i = 0; i < 4; i++) { acc[i][0] = 0ull; acc[i][1] = 0ull; }
    gemm_tile<64, 64>(buf1, w3, tr, tc, acc);

    float l[4][4], ssq[4];
#pragma unroll
    for (int i = 0; i < 4; i++) {
        float p0, p1, p2, p3;
        unpack2(acc[i][0], p0, p1); unpack2(acc[i][1], p2, p3);
        float4 lr = *(const float4*)&buf3[(tr + i) * 64 + tc];
        l[i][0] = lr.x * (1.f + p0);
        l[i][1] = lr.y * (1.f + p1);
        l[i][2] = lr.z * (1.f + p2);
        l[i][3] = lr.w * (1.f + p3);
        ssq[i] = l[i][0]*l[i][0] + l[i][1]*l[i][1] + l[i][2]*l[i][2] + l[i][3]*l[i][3];
    }
#pragma unroll
    for (int m = 1; m < 16; m <<= 1) {
#pragma unroll
        for (int i = 0; i < 4; i++)
            ssq[i] += __shfl_xor_sync(0xffffffffu, ssq[i], m);
    }
#pragma unroll
    for (int i = 0; i < 4; i++) {
        float inv = 1.f / fmaxf(sqrtf(ssq[i]), 1e-12f);
        *(float4*)&buf3[(tr + i) * 64 + tc] =
            make_float4(l[i][0]*inv, l[i][1]*inv, l[i][2]*inv, l[i][3]*inv);
    }
    __syncthreads();

    {
        u64 bias0 = pack2(b1s[tc], b1s[tc + 1]);
        u64 bias1 = pack2(b1s[tc + 2], b1s[tc + 3]);
#pragma unroll
        for (int i = 0; i < 4; i++) { acc[i][0] = bias0; acc[i][1] = bias1; }
    }
    gemm_tile<128, 128>(buf2, wn1, tr, tc, acc);
#pragma unroll
    for (int i = 0; i < 4; i++) {
        float s0, s1, s2, s3;
        unpack2(acc[i][0], s0, s1); unpack2(acc[i][1], s2, s3);
        *(float4*)&buf1[(tr + i) * 64 + tc] =
            make_float4(silu_f(s0), silu_f(s1), silu_f(s2), silu_f(s3));
    }
    __syncthreads();

    float nf[4][4];
    {
        u64 bias0 = pack2(b2s[tc], b2s[tc + 1]);
        u64 bias1 = pack2(b2s[tc + 2], b2s[tc + 3]);
#pragma unroll
        for (int i = 0; i < 4; i++) { acc[i][0] = bias0; acc[i][1] = bias1; }
    }
    gemm_tile<64, 64>(buf1, wn2, tr, tc, acc);
#pragma unroll
    for (int i = 0; i < 4; i++) {
        float s0, s1, s2, s3;
        unpack2(acc[i][0], s0, s1); unpack2(acc[i][1], s2, s3);
        nf[i][0] = silu_f(s0); nf[i][1] = silu_f(s1);
        nf[i][2] = silu_f(s2); nf[i][3] = silu_f(s3);
    }

#pragma unroll
    for (int i = 0; i < 4; i++) { acc[i][0] = 0ull; acc[i][1] = 0ull; }
    gemm_tile<64, 64>(buf3, wb, tr, tc, acc);
#pragma unroll
    for (int i = 0; i < 4; i++) {
        int e = e0 + tr + i;
        if (e < N_EDGES) {
            float m0, m1, m2, m3;
            unpack2(acc[i][0], m0, m1); unpack2(acc[i][1], m2, m3);
            red4(&g_agg[(size_t)es[tr + i] * CONV + tc],
                 m0 * nf[i][0], m1 * nf[i][1], m2 * nf[i][2], m3 * nf[i][3]);
        }
    }
}

// ---------- K5: out = x + agg @ W_out, 4 nodes/block ----------
__global__ void __launch_bounds__(128) k_out(const float* __restrict__ x,
                                             const float* __restrict__ Wout,
                                             float* __restrict__ out) {
    __shared__ float ags[4][CONV];
    int n0 = blockIdx.x * 4, j = threadIdx.x;
    if (j < 2 * CONV) {
        int v = j >> 6, c = j & 63;
        ags[v][c]     = g_agg[(size_t)(n0 + v) * CONV + c];
        ags[v + 2][c] = g_agg[(size_t)(n0 + v + 2) * CONV + c];
    }
    __syncthreads();
    float a0 = 0.f, a1 = 0.f, a2 = 0.f, a3 = 0.f;
#pragma unroll 4
    for (int k = 0; k < CONV; k++) {
        float w = Wout[k * EMB + j];
        a0 = fmaf(ags[0][k], w, a0);
        a1 = fmaf(ags[1][k], w, a1);
        a2 = fmaf(ags[2][k], w, a2);
        a3 = fmaf(ags[3][k], w, a3);
    }
    out[(size_t)(n0 + 0) * EMB + j] = x[(size_t)(n0 + 0) * EMB + j] + a0;
    out[(size_t)(n0 + 1) * EMB + j] = x[(size_t)(n0 + 1) * EMB + j] + a1;
    out[(size_t)(n0 + 2) * EMB + j] = x[(size_t)(n0 + 2) * EMB + j] + a2;
    out[(size_t)(n0 + 3) * EMB + j] = x[(size_t)(n0 + 3) * EMB + j] + a3;
}

extern "C" void kernel_launch(void* const* d_in, const int* in_sizes, int n_in,
                              void* d_out, int out_size) {
    const float* x      = (const float*)d_in[0];
    const float* cst    = (const float*)d_in[1];
    const float* rb     = (const float*)d_in[2];
    const float* shb    = (const float*)d_in[3];
    const int*   idx_s  = (const int*)  d_in[4];
    const int*   idx_t  = (const int*)  d_in[5];
    const int*   tri_k  = (const int*)  d_in[6];
    const int*   eks    = (const int*)  d_in[7];
    const int*   est    = (const int*)  d_in[8];
    const float* W_node = (const float*)d_in[9];
    const float* b_node = (const float*)d_in[10];
    const float* W_c1   = (const float*)d_in[11];
    const float* W_c2   = (const float*)d_in[12];
    const float* W_three= (const float*)d_in[13];
    const float* W_basis= (const float*)d_in[14];
    const float* W_n1   = (const float*)d_in[15];
    const float* b_n1   = (const float*)d_in[16];
    const float* W_n2   = (const float*)d_in[17];
    const float* b_n2   = (const float*)d_in[18];
    const float* W_out  = (const float*)d_in[19];
    float* out = (float*)d_out;

    cudaFuncSetAttribute(k_edge,    cudaFuncAttributeMaxDynamicSharedMemorySize, EDGE_SMEM_BYTES);
    cudaFuncSetAttribute(k_cst_mma, cudaFuncAttributeMaxDynamicSharedMemorySize, CST_SMEM_BYTES);

    const int zero_total = N_EDGES * CONV + N_NODES * CONV;
    k_zero<<<(zero_total + 255) / 256, 256>>>();
    k_node<<<N_NODES / 4, 128>>>(x, W_node, b_node);
    k_prepw<<<1, 256>>>(W_c1, W_c2);
    k_cst_mma<<<(N_EDGES * NORB) / 256, 256, CST_SMEM_BYTES>>>(cst, rb);
    k_tri <<<(N_TRI * 32) / 256, 256>>>(rb, shb, tri_k, eks, est);
    k_edge<<<(N_EDGES + 63) / 64, 256, EDGE_SMEM_BYTES>>>(idx_s, idx_t, W_three, W_basis,
                                                          W_n1, b_n1, W_n2, b_n2);
    k_out <<<N_NODES / 4, 128>>>(x, W_out, out);
}

// round 6
// speedup vs baseline: 2.1798x; 1.4181x over previous
#include <cuda_runtime.h>
#include <cuda_bf16.h>
#include <math.h>
#include <stdint.h>

#define N_NODES 20000
#define N_EDGES 100000
#define N_TRI   200000
#define NORB    16
#define EMB     128
#define CONV    64

typedef unsigned long long u64;

__device__ __forceinline__ float silu_f(float x) { return x / (1.f + __expf(-x)); }
__device__ __forceinline__ float sigmoid_f(float x) { return 1.f / (1.f + __expf(-x)); }
__device__ __forceinline__ void red2(float* p, float a, float b) {
    asm volatile("red.global.add.v2.f32 [%0], {%1, %2};" :: "l"(p), "f"(a), "f"(b) : "memory");
}
__device__ __forceinline__ uint32_t smem_u32(const void* p) {
    uint32_t a;
    asm("{ .reg .u64 t; cvta.to.shared.u64 t, %1; cvt.u32.u64 %0, t; }" : "=r"(a) : "l"(p));
    return a;
}
// portable bf16 m16n8k16 mma -> HMMA on tensor pipe
__device__ __forceinline__ void mma_bf16(float d[4], const uint32_t a[4],
                                         uint32_t b0, uint32_t b1) {
    asm("mma.sync.aligned.m16n8k16.row.col.f32.bf16.bf16.f32 "
        "{%0,%1,%2,%3}, {%4,%5,%6,%7}, {%8,%9}, {%0,%1,%2,%3};"
        : "+f"(d[0]), "+f"(d[1]), "+f"(d[2]), "+f"(d[3])
        : "r"(a[0]), "r"(a[1]), "r"(a[2]), "r"(a[3]), "r"(b0), "r"(b1));
}
__device__ __forceinline__ void ldmx4(uint32_t &r0, uint32_t &r1, uint32_t &r2,
                                      uint32_t &r3, uint32_t addr) {
    asm volatile("ldmatrix.sync.aligned.m8n8.x4.shared.b16 {%0,%1,%2,%3}, [%4];"
                 : "=r"(r0), "=r"(r1), "=r"(r2), "=r"(r3) : "r"(addr));
}
__device__ __forceinline__ unsigned bf2x(float lo, float hi) {
    __nv_bfloat162 h = __float22bfloat162_rn(make_float2(lo, hi));
    return *reinterpret_cast<unsigned*>(&h);
}

// fragment byte-offset helpers (stride in bf16 elements)
// A tile (16 rows x 16 k): lanes 0-15 -> rows 0-15 @k0, lanes 16-31 -> rows @k0+8
#define A_OFF(lane, ld) ((uint32_t)(((lane) & 15) * (ld) + (((lane) >> 4) << 3)) * 2u)
// B tile (16 n x 16 k), [n][k] layout
#define B_OFF(lane, ld) ((uint32_t)(((((lane) >> 4) << 3) + ((lane) & 7)) * (ld) + \
                                    ((((lane) >> 3) & 1) << 3)) * 2u)

// ---------- scratch ----------
__device__ float g_x1   [(size_t)N_NODES * CONV];
__device__ float g_xksig[(size_t)N_NODES * CONV];
__device__ __align__(16) __nv_bfloat16 g_cst2h[(size_t)N_EDGES * NORB * CONV];
__device__ float g_lraw [(size_t)N_EDGES * CONV];
__device__ float g_tbw  [(size_t)N_EDGES * CONV];
__device__ float g_agg  [(size_t)N_NODES * CONV];
__device__ __align__(16) __nv_bfloat16 g_w1h[4096];   // W1^T bf16, [n][k]
__device__ __align__(16) __nv_bfloat16 g_w2h[4096];   // W2^T bf16, [n][k]

// ---------- zero atomic targets ----------
__global__ void k_zero() {
    int i = blockIdx.x * blockDim.x + threadIdx.x;
    const int t1 = N_EDGES * CONV;
    const int total = t1 + N_NODES * CONV;
    if (i < total) {
        if (i < t1) g_tbw[i] = 0.f;
        else        g_agg[i - t1] = 0.f;
    }
}

// ---------- prep: W (in,out) -> W^T [n][k] bf16 ----------
__global__ void k_prepw(const float* __restrict__ W1, const float* __restrict__ W2) {
    for (int i = threadIdx.x; i < 4096; i += 256) {
        int n = i >> 6, k = i & 63;
        g_w1h[i] = __float2bfloat16(W1[k * 64 + n]);
        g_w2h[i] = __float2bfloat16(W2[k * 64 + n]);
    }
}

// ---------- K1: node transform, 4 nodes/block ----------
__global__ void __launch_bounds__(128) k_node(const float* __restrict__ x,
                                              const float* __restrict__ Wn,
                                              const float* __restrict__ bn) {
    __shared__ float xs[4][EMB];
    int n0 = blockIdx.x * 4, j = threadIdx.x;
#pragma unroll
    for (int v = 0; v < 4; v++)
        xs[v][j] = x[(size_t)(n0 + v) * EMB + j];
    __syncthreads();
    float a0 = bn[j], a1 = a0, a2 = a0, a3 = a0;
#pragma unroll 4
    for (int k = 0; k < EMB; k++) {
        float w = Wn[k * EMB + j];
        a0 = fmaf(xs[0][k], w, a0);
        a1 = fmaf(xs[1][k], w, a1);
        a2 = fmaf(xs[2][k], w, a2);
        a3 = fmaf(xs[3][k], w, a3);
    }
    if (j < CONV) {
        g_x1[(size_t)(n0 + 0) * CONV + j] = a0;
        g_x1[(size_t)(n0 + 1) * CONV + j] = a1;
        g_x1[(size_t)(n0 + 2) * CONV + j] = a2;
        g_x1[(size_t)(n0 + 3) * CONV + j] = a3;
    } else {
        int jj = j - CONV;
        g_xksig[(size_t)(n0 + 0) * CONV + jj] = sigmoid_f(a0);
        g_xksig[(size_t)(n0 + 1) * CONV + jj] = sigmoid_f(a1);
        g_xksig[(size_t)(n0 + 2) * CONV + jj] = sigmoid_f(a2);
        g_xksig[(size_t)(n0 + 3) * CONV + jj] = sigmoid_f(a3);
    }
}

// ---------- K2: bf16 mma double GEMM, 1 m16-tile (1 edge) per warp ----------
#define LDB 72
#define CST_SMEM_BYTES ((128 * LDB + 2 * 64 * LDB) * 2)   // 36864 B
__global__ void __launch_bounds__(256, 3) k_cst_mma(const float* __restrict__ A,
                                                    const float* __restrict__ rb) {
    extern __shared__ __align__(16) __nv_bfloat16 sb[];
    __nv_bfloat16* sA  = sb;                   // 128 x 72
    __nv_bfloat16* sW1 = sb + 128 * LDB;       // 64 x 72
    __nv_bfloat16* sW2 = sW1 + 64 * LDB;
    const uint32_t sAu  = smem_u32(sA);
    const uint32_t sW1u = smem_u32(sW1);
    const uint32_t sW2u = smem_u32(sW2);

    const int tid = threadIdx.x, wid = tid >> 5, lane = tid & 31;
    const int g = lane >> 2, tg = lane & 3;
    const int wr0 = wid * 16;

    for (int i = tid; i < 512; i += 256) {
        int n = i >> 3, kc = i & 7;
        *(uint4*)(sW1 + n * LDB + kc * 8) = ((const uint4*)g_w1h)[i];
        *(uint4*)(sW2 + n * LDB + kc * 8) = ((const uint4*)g_w2h)[i];
    }
    const float4* Ag = (const float4*)(A + (size_t)blockIdx.x * (128 * 64));
    for (int i = tid; i < 2048; i += 256) {
        int r = i >> 4, c4 = i & 15;
        float4 v = Ag[i];
        *(uint2*)(sA + r * LDB + c4 * 4) = make_uint2(bf2x(v.x, v.y), bf2x(v.z, v.w));
    }
    __syncthreads();

    const uint32_t a_off = A_OFF(lane, LDB);
    const uint32_t b_off = B_OFF(lane, LDB);

    float acc[8][4];
    uint32_t a[4];

    // ---- stage 1 ----
#pragma unroll
    for (int at = 0; at < 8; at++)
#pragma unroll
        for (int q = 0; q < 4; q++) acc[at][q] = 0.f;
#pragma unroll
    for (int ks = 0; ks < 4; ks++) {
        const int k0 = ks * 16;
        ldmx4(a[0], a[1], a[2], a[3], sAu + a_off + (uint32_t)(wr0 * LDB + k0) * 2);
#pragma unroll
        for (int np = 0; np < 4; np++) {
            uint32_t b0, b1, b2, b3;
            ldmx4(b0, b1, b2, b3, sW1u + b_off + (uint32_t)(np * 16 * LDB + k0) * 2);
            mma_bf16(acc[2 * np],     a, b0, b1);
            mma_bf16(acc[2 * np + 1], a, b2, b3);
        }
    }
#pragma unroll
    for (int at = 0; at < 8; at++) {
        int c = at * 8 + 2 * tg;
        *(unsigned*)(sA + (wr0 + g) * LDB + c) =
            bf2x(silu_f(acc[at][0]), silu_f(acc[at][1]));
        *(unsigned*)(sA + (wr0 + g + 8) * LDB + c) =
            bf2x(silu_f(acc[at][2]), silu_f(acc[at][3]));
    }
    __syncwarp();

    // ---- stage 2 ----
#pragma unroll
    for (int at = 0; at < 8; at++)
#pragma unroll
        for (int q = 0; q < 4; q++) acc[at][q] = 0.f;
#pragma unroll
    for (int ks = 0; ks < 4; ks++) {
        const int k0 = ks * 16;
        ldmx4(a[0], a[1], a[2], a[3], sAu + a_off + (uint32_t)(wr0 * LDB + k0) * 2);
#pragma unroll
        for (int np = 0; np < 4; np++) {
            uint32_t b0, b1, b2, b3;
            ldmx4(b0, b1, b2, b3, sW2u + b_off + (uint32_t)(np * 16 * LDB + k0) * 2);
            mma_bf16(acc[2 * np],     a, b0, b1);
            mma_bf16(acc[2 * np + 1], a, b2, b3);
        }
    }
    __syncwarp();

    // ---- epilogue: silu, lraw, bf16 store ----
    {
        const int edge = blockIdx.x * 8 + wid;
        float rbl = (lane < NORB) ? rb[(size_t)edge * NORB + lane] : 0.f;
        float rbg  = __shfl_sync(0xffffffffu, rbl, g);
        float rbg8 = __shfl_sync(0xffffffffu, rbl, g + 8);
#pragma unroll
        for (int at = 0; at < 8; at++) {
            float v0 = silu_f(acc[at][0]);
            float v1 = silu_f(acc[at][1]);
            float v2 = silu_f(acc[at][2]);
            float v3 = silu_f(acc[at][3]);
            int c = at * 8 + 2 * tg;
            *(unsigned*)(sA + (wr0 + g) * LDB + c)     = bf2x(v0, v1);
            *(unsigned*)(sA + (wr0 + g + 8) * LDB + c) = bf2x(v2, v3);
            float c0 = rbg * v0 + rbg8 * v2;
            float c1 = rbg * v1 + rbg8 * v3;
#pragma unroll
            for (int o = 4; o < 32; o <<= 1) {
                c0 += __shfl_xor_sync(0xffffffffu, c0, o);
                c1 += __shfl_xor_sync(0xffffffffu, c1, o);
            }
            if (lane < 4)
                *(float2*)&g_lraw[(size_t)edge * CONV + at * 8 + 2 * tg] =
                    make_float2(c0, c1);
        }
    }
    __syncwarp();
    {
        int r = wr0 + (lane >> 1);
        int j0 = (lane & 1) * 4;
        size_t grow = (size_t)blockIdx.x * 128 + r;
        uint4* dst = (uint4*)(g_cst2h + grow * 64);
        const __nv_bfloat16* src = sA + r * LDB;
#pragma unroll
        for (int j = 0; j < 4; j++)
            dst[j0 + j] = *(const uint4*)(src + (j0 + j) * 8);
    }
}

// ---------- K3: triplet kernel ----------
__global__ void __launch_bounds__(256) k_tri(const float* __restrict__ rb,
                                             const float* __restrict__ shb,
                                             const int*   __restrict__ tri_k,
                                             const int*   __restrict__ eks,
                                             const int*   __restrict__ est) {
    int t = (blockIdx.x * blockDim.x + threadIdx.x) >> 5;
    int lane = threadIdx.x & 31;
    if (t >= N_TRI) return;
    int e = eks[t], knode = tri_k[t], eo = est[t];

    float cl = (lane < NORB) ? rb[(size_t)e * NORB + lane] * shb[(size_t)t * NORB + lane] : 0.f;

    const __nv_bfloat162* C = (const __nv_bfloat162*)(g_cst2h + (size_t)e * (NORB * CONV));
    float a0 = 0.f, a1 = 0.f;
#pragma unroll
    for (int d = 0; d < NORB; d++) {
        float c = __shfl_sync(0xffffffffu, cl, d);
        float2 v = __bfloat1622float2(C[d * 32 + lane]);
        a0 = fmaf(c, v.x, a0);
        a1 = fmaf(c, v.y, a1);
    }
    float ss = a0 * a0 + a1 * a1;
#pragma unroll
    for (int o = 16; o; o >>= 1) ss += __shfl_xor_sync(0xffffffffu, ss, o);
    float inv = 1.f / fmaxf(sqrtf(ss), 1e-12f);

    float2 sg = *(const float2*)(g_xksig + (size_t)knode * CONV + 2 * lane);
    red2(&g_tbw[(size_t)eo * CONV + 2 * lane], a0 * inv * sg.x, a1 * inv * sg.y);
}

// ---------- K4: bf16 mma edge kernel, 128 edges/block, 8 warps (1 m16 tile each) ----------
// bf16 elem offsets within extern smem:
//  sW3 0 (64x72) | sWB 4608 | sWN2 9216 | sWN1 13824 (64x136) | sTW 22528 (128x72) | sCAT 31744 (128x136)
//  then fp32 b1[64], b2[64]; int es[128], et[128]
#define E_W3   0
#define E_WB   4608
#define E_WN2  9216
#define E_WN1  13824
#define E_TW   22528
#define E_CAT  31744
#define E_END  49152
#define LDC    136
#define EDGE_SMEM_BYTES (E_END * 2 + 512 + 1024)
__global__ void __launch_bounds__(256, 2) k_edge(const int* __restrict__ idx_s,
                                                 const int* __restrict__ idx_t,
                                                 const float* __restrict__ W3g,
                                                 const float* __restrict__ Wbg,
                                                 const float* __restrict__ Wn1g,
                                                 const float* __restrict__ bn1g,
                                                 const float* __restrict__ Wn2g,
                                                 const float* __restrict__ bn2g) {
    extern __shared__ __align__(16) __nv_bfloat16 sb[];
    __nv_bfloat16* sW3  = sb + E_W3;
    __nv_bfloat16* sWB  = sb + E_WB;
    __nv_bfloat16* sWN2 = sb + E_WN2;
    __nv_bfloat16* sWN1 = sb + E_WN1;
    __nv_bfloat16* sTW  = sb + E_TW;
    __nv_bfloat16* sCAT = sb + E_CAT;
    float* b1s = (float*)(sb + E_END);
    float* b2s = b1s + 64;
    int*   es  = (int*)(b2s + 64);
    int*   et  = es + 128;
    const uint32_t sW3u  = smem_u32(sW3);
    const uint32_t sWBu  = smem_u32(sWB);
    const uint32_t sWN2u = smem_u32(sWN2);
    const uint32_t sWN1u = smem_u32(sWN1);
    const uint32_t sTWu  = smem_u32(sTW);
    const uint32_t sCATu = smem_u32(sCAT);

    const int tid = threadIdx.x, wid = tid >> 5, lane = tid & 31;
    const int g = lane >> 2, tg = lane & 3;
    const int wr0 = wid * 16;
    const int e0 = blockIdx.x * 128;

    // weights -> bf16 smem, transposed to [n][k]
    for (int i = tid; i < 4096; i += 256) {
        int k = i >> 6, n = i & 63;
        sW3 [n * LDB + k] = __float2bfloat16(W3g[i]);
        sWB [n * LDB + k] = __float2bfloat16(Wbg[i]);
        sWN2[n * LDB + k] = __float2bfloat16(Wn2g[i]);
    }
    for (int i = tid; i < 8192; i += 256) {
        int k = i >> 6, n = i & 63;
        sWN1[n * LDC + k] = __float2bfloat16(Wn1g[i]);
    }
    if (tid < 64) { b1s[tid] = bn1g[tid]; b2s[tid] = bn2g[tid]; }
    if (tid < 128) {
        int e = e0 + tid;
        es[tid] = (e < N_EDGES) ? idx_s[e] : 0;
        et[tid] = (e < N_EDGES) ? idx_t[e] : 0;
    }
    // tw -> bf16 smem
    for (int i = tid; i < 2048; i += 256) {
        int r = i >> 4, c4 = i & 15;
        float4 v = (e0 + r < N_EDGES) ? ((const float4*)g_tbw)[(size_t)(e0 + r) * 16 + c4]
                                      : make_float4(0.f, 0.f, 0.f, 0.f);
        *(uint2*)(sTW + r * LDB + c4 * 4) = make_uint2(bf2x(v.x, v.y), bf2x(v.z, v.w));
    }
    __syncthreads();   // es/et visible for cat gather

    // cat = [x1[s] | x1[t]] -> bf16 smem
    for (int i = tid; i < 4096; i += 256) {
        int r = i >> 5, c4 = i & 31;
        int node = (c4 < 16) ? es[r] : et[r];
        float4 v = (e0 + r < N_EDGES) ? ((const float4*)g_x1)[(size_t)node * 16 + (c4 & 15)]
                                      : make_float4(0.f, 0.f, 0.f, 0.f);
        *(uint2*)(sCAT + r * LDC + c4 * 4) = make_uint2(bf2x(v.x, v.y), bf2x(v.z, v.w));
    }
    __syncthreads();

    const uint32_t a_offB = A_OFF(lane, LDB);
    const uint32_t b_offB = B_OFF(lane, LDB);
    const uint32_t a_offC = A_OFF(lane, LDC);
    const uint32_t b_offC = B_OFF(lane, LDC);

    float acc[8][4];
    uint32_t a[4];

    // ---- GEMM1: proj = tw @ W3 ----
#pragma unroll
    for (int at = 0; at < 8; at++)
#pragma unroll
        for (int q = 0; q < 4; q++) acc[at][q] = 0.f;
#pragma unroll
    for (int ks = 0; ks < 4; ks++) {
        const int k0 = ks * 16;
        ldmx4(a[0], a[1], a[2], a[3], sTWu + a_offB + (uint32_t)(wr0 * LDB + k0) * 2);
#pragma unroll
        for (int np = 0; np < 4; np++) {
            uint32_t b0, b1, b2, b3;
            ldmx4(b0, b1, b2, b3, sW3u + b_offB + (uint32_t)(np * 16 * LDB + k0) * 2);
            mma_bf16(acc[2 * np],     a, b0, b1);
            mma_bf16(acc[2 * np + 1], a, b2, b3);
        }
    }
    // lc = normalize(lraw * (1 + proj)) ; write bf16 into sTW (own rows)
    {
        size_t eg  = (size_t)(e0 + wr0 + g);
        size_t eg8 = eg + 8;
        bool ok0 = eg  < N_EDGES;
        bool ok8 = eg8 < N_EDGES;
        float s0 = 0.f, s8 = 0.f;
#pragma unroll
        for (int at = 0; at < 8; at++) {
            int c = at * 8 + 2 * tg;
            float2 l0 = ok0 ? *(const float2*)&g_lraw[eg * CONV + c]  : make_float2(0.f, 0.f);
            float2 l8 = ok8 ? *(const float2*)&g_lraw[eg8 * CONV + c] : make_float2(0.f, 0.f);
            acc[at][0] = l0.x * (1.f + acc[at][0]);
            acc[at][1] = l0.y * (1.f + acc[at][1]);
            acc[at][2] = l8.x * (1.f + acc[at][2]);
            acc[at][3] = l8.y * (1.f + acc[at][3]);
            s0 += acc[at][0] * acc[at][0] + acc[at][1] * acc[at][1];
            s8 += acc[at][2] * acc[at][2] + acc[at][3] * acc[at][3];
        }
#pragma unroll
        for (int o = 1; o < 4; o <<= 1) {
            s0 += __shfl_xor_sync(0xffffffffu, s0, o);
            s8 += __shfl_xor_sync(0xffffffffu, s8, o);
        }
        float i0 = 1.f / fmaxf(sqrtf(s0), 1e-12f);
        float i8 = 1.f / fmaxf(sqrtf(s8), 1e-12f);
#pragma unroll
        for (int at = 0; at < 8; at++) {
            int c = at * 8 + 2 * tg;
            *(unsigned*)(sTW + (wr0 + g) * LDB + c)     = bf2x(acc[at][0] * i0, acc[at][1] * i0);
            *(unsigned*)(sTW + (wr0 + g + 8) * LDB + c) = bf2x(acc[at][2] * i8, acc[at][3] * i8);
        }
    }
    __syncwarp();

    // ---- GEMM2: n1 = silu(cat @ Wn1 + b1) -> sCAT own rows ----
#pragma unroll
    for (int at = 0; at < 8; at++) {
        int c = at * 8 + 2 * tg;
        acc[at][0] = b1s[c]; acc[at][1] = b1s[c + 1];
        acc[at][2] = acc[at][0]; acc[at][3] = acc[at][1];
    }
#pragma unroll
    for (int ks = 0; ks < 8; ks++) {
        const int k0 = ks * 16;
        ldmx4(a[0], a[1], a[2], a[3], sCATu + a_offC + (uint32_t)(wr0 * LDC + k0) * 2);
#pragma unroll
        for (int np = 0; np < 4; np++) {
            uint32_t b0, b1, b2, b3;
            ldmx4(b0, b1, b2, b3, sWN1u + b_offC + (uint32_t)(np * 16 * LDC + k0) * 2);
            mma_bf16(acc[2 * np],     a, b0, b1);
            mma_bf16(acc[2 * np + 1], a, b2, b3);
        }
    }
#pragma unroll
    for (int at = 0; at < 8; at++) {
        int c = at * 8 + 2 * tg;
        *(unsigned*)(sCAT + (wr0 + g) * LDC + c) =
            bf2x(silu_f(acc[at][0]), silu_f(acc[at][1]));
        *(unsigned*)(sCAT + (wr0 + g + 8) * LDC + c) =
            bf2x(silu_f(acc[at][2]), silu_f(acc[at][3]));
    }
    __syncwarp();

    // ---- GEMM3: nf = silu(n1 @ Wn2 + b2) (keep in regs) ----
    float nf[8][4];
#pragma unroll
    for (int at = 0; at < 8; at++) {
        int c = at * 8 + 2 * tg;
        nf[at][0] = b2s[c]; nf[at][1] = b2s[c + 1];
        nf[at][2] = nf[at][0]; nf[at][3] = nf[at][1];
    }
#pragma unroll
    for (int ks = 0; ks < 4; ks++) {
        const int k0 = ks * 16;
        ldmx4(a[0], a[1], a[2], a[3], sCATu + a_offC + (uint32_t)(wr0 * LDC + k0) * 2);
#pragma unroll
        for (int np = 0; np < 4; np++) {
            uint32_t b0, b1, b2, b3;
            ldmx4(b0, b1, b2, b3, sWN2u + b_offB + (uint32_t)(np * 16 * LDB + k0) * 2);
            mma_bf16(nf[2 * np],     a, b0, b1);
            mma_bf16(nf[2 * np + 1], a, b2, b3);
        }
    }
#pragma unroll
    for (int at = 0; at < 8; at++)
#pragma unroll
        for (int q = 0; q < 4; q++) nf[at][q] = silu_f(nf[at][q]);

    // ---- GEMM4: m = lc @ Wb ----
#pragma unroll
    for (int at = 0; at < 8; at++)
#pragma unroll
        for (int q = 0; q < 4; q++) acc[at][q] = 0.f;
#pragma unroll
    for (int ks = 0; ks < 4; ks++) {
        const int k0 = ks * 16;
        ldmx4(a[0], a[1], a[2], a[3], sTWu + a_offB + (uint32_t)(wr0 * LDB + k0) * 2);
#pragma unroll
        for (int np = 0; np < 4; np++) {
            uint32_t b0, b1, b2, b3;
            ldmx4(b0, b1, b2, b3, sWBu + b_offB + (uint32_t)(np * 16 * LDB + k0) * 2);
            mma_bf16(acc[2 * np],     a, b0, b1);
            mma_bf16(acc[2 * np + 1], a, b2, b3);
        }
    }

    // ---- scatter msg = m * nf by idx_s ----
    {
        int rg = wr0 + g;
        int ns0 = es[rg], ns8 = es[rg + 8];
        bool ok0 = (e0 + rg) < N_EDGES;
        bool ok8 = (e0 + rg + 8) < N_EDGES;
#pragma unroll
        for (int at = 0; at < 8; at++) {
            int c = at * 8 + 2 * tg;
            if (ok0) red2(&g_agg[(size_t)ns0 * CONV + c],
                          acc[at][0] * nf[at][0], acc[at][1] * nf[at][1]);
            if (ok8) red2(&g_agg[(size_t)ns8 * CONV + c],
                          acc[at][2] * nf[at][2], acc[at][3] * nf[at][3]);
        }
    }
}

// ---------- K5: out = x + agg @ W_out, 4 nodes/block ----------
__global__ void __launch_bounds__(128) k_out(const float* __restrict__ x,
                                             const float* __restrict__ Wout,
                                             float* __restrict__ out) {
    __shared__ float ags[4][CONV];
    int n0 = blockIdx.x * 4, j = threadIdx.x;
    if (j < 2 * CONV) {
        int v = j >> 6, c = j & 63;
        ags[v][c]     = g_agg[(size_t)(n0 + v) * CONV + c];
        ags[v + 2][c] = g_agg[(size_t)(n0 + v + 2) * CONV + c];
    }
    __syncthreads();
    float a0 = 0.f, a1 = 0.f, a2 = 0.f, a3 = 0.f;
#pragma unroll 4
    for (int k = 0; k < CONV; k++) {
        float w = Wout[k * EMB + j];
        a0 = fmaf(ags[0][k], w, a0);
        a1 = fmaf(ags[1][k], w, a1);
        a2 = fmaf(ags[2][k], w, a2);
        a3 = fmaf(ags[3][k], w, a3);
    }
    out[(size_t)(n0 + 0) * EMB + j] = x[(size_t)(n0 + 0) * EMB + j] + a0;
    out[(size_t)(n0 + 1) * EMB + j] = x[(size_t)(n0 + 1) * EMB + j] + a1;
    out[(size_t)(n0 + 2) * EMB + j] = x[(size_t)(n0 + 2) * EMB + j] + a2;
    out[(size_t)(n0 + 3) * EMB + j] = x[(size_t)(n0 + 3) * EMB + j] + a3;
}

extern "C" void kernel_launch(void* const* d_in, const int* in_sizes, int n_in,
                              void* d_out, int out_size) {
    const float* x      = (const float*)d_in[0];
    const float* cst    = (const float*)d_in[1];
    const float* rb     = (const float*)d_in[2];
    const float* shb    = (const float*)d_in[3];
    const int*   idx_s  = (const int*)  d_in[4];
    const int*   idx_t  = (const int*)  d_in[5];
    const int*   tri_k  = (const int*)  d_in[6];
    const int*   eks    = (const int*)  d_in[7];
    const int*   est    = (const int*)  d_in[8];
    const float* W_node = (const float*)d_in[9];
    const float* b_node = (const float*)d_in[10];
    const float* W_c1   = (const float*)d_in[11];
    const float* W_c2   = (const float*)d_in[12];
    const float* W_three= (const float*)d_in[13];
    const float* W_basis= (const float*)d_in[14];
    const float* W_n1   = (const float*)d_in[15];
    const float* b_n1   = (const float*)d_in[16];
    const float* W_n2   = (const float*)d_in[17];
    const float* b_n2   = (const float*)d_in[18];
    const float* W_out  = (const float*)d_in[19];
    float* out = (float*)d_out;

    cudaFuncSetAttribute(k_edge,    cudaFuncAttributeMaxDynamicSharedMemorySize, EDGE_SMEM_BYTES);
    cudaFuncSetAttribute(k_cst_mma, cudaFuncAttributeMaxDynamicSharedMemorySize, CST_SMEM_BYTES);

    const int zero_total = N_EDGES * CONV + N_NODES * CONV;
    k_zero<<<(zero_total + 255) / 256, 256>>>();
    k_node<<<N_NODES / 4, 128>>>(x, W_node, b_node);
    k_prepw<<<1, 256>>>(W_c1, W_c2);
    k_cst_mma<<<(N_EDGES * NORB) / 128, 256, CST_SMEM_BYTES>>>(cst, rb);
    k_tri <<<(N_TRI * 32) / 256, 256>>>(rb, shb, tri_k, eks, est);
    k_edge<<<(N_EDGES + 127) / 128, 256, EDGE_SMEM_BYTES>>>(idx_s, idx_t, W_three, W_basis,
                                                            W_n1, b_n1, W_n2, b_n2);
    k_out <<<N_NODES / 4, 128>>>(x, W_out, out);
}

// round 7
// speedup vs baseline: 2.2107x; 1.0142x over previous
#include <cuda_runtime.h>
#include <cuda_bf16.h>
#include <math.h>
#include <stdint.h>

#define N_NODES 20000
#define N_EDGES 100000
#define N_TRI   200000
#define NORB    16
#define EMB     128
#define CONV    64

typedef unsigned long long u64;

__device__ __forceinline__ float silu_f(float x) { return x / (1.f + __expf(-x)); }
__device__ __forceinline__ float sigmoid_f(float x) { return 1.f / (1.f + __expf(-x)); }
__device__ __forceinline__ void red2(float* p, float a, float b) {
    asm volatile("red.global.add.v2.f32 [%0], {%1, %2};" :: "l"(p), "f"(a), "f"(b) : "memory");
}
__device__ __forceinline__ uint32_t smem_u32(const void* p) {
    uint32_t a;
    asm("{ .reg .u64 t; cvta.to.shared.u64 t, %1; cvt.u32.u64 %0, t; }" : "=r"(a) : "l"(p));
    return a;
}
__device__ __forceinline__ void mma_bf16(float d[4], const uint32_t a[4],
                                         uint32_t b0, uint32_t b1) {
    asm("mma.sync.aligned.m16n8k16.row.col.f32.bf16.bf16.f32 "
        "{%0,%1,%2,%3}, {%4,%5,%6,%7}, {%8,%9}, {%0,%1,%2,%3};"
        : "+f"(d[0]), "+f"(d[1]), "+f"(d[2]), "+f"(d[3])
        : "r"(a[0]), "r"(a[1]), "r"(a[2]), "r"(a[3]), "r"(b0), "r"(b1));
}
__device__ __forceinline__ void ldmx4(uint32_t &r0, uint32_t &r1, uint32_t &r2,
                                      uint32_t &r3, uint32_t addr) {
    asm volatile("ldmatrix.sync.aligned.m8n8.x4.shared.b16 {%0,%1,%2,%3}, [%4];"
                 : "=r"(r0), "=r"(r1), "=r"(r2), "=r"(r3) : "r"(addr));
}
__device__ __forceinline__ unsigned bf2x(float lo, float hi) {
    __nv_bfloat162 h = __float22bfloat162_rn(make_float2(lo, hi));
    return *reinterpret_cast<unsigned*>(&h);
}

// A tile (16 rows x 16 k): lanes 0-15 -> rows 0-15 @k0, lanes 16-31 -> rows @k0+8
#define A_OFF(lane, ld) ((uint32_t)(((lane) & 15) * (ld) + (((lane) >> 4) << 3)) * 2u)
// B tile (16 n x 16 k), [n][k] layout
#define B_OFF(lane, ld) ((uint32_t)(((((lane) >> 4) << 3) + ((lane) & 7)) * (ld) + \
                                    ((((lane) >> 3) & 1) << 3)) * 2u)

// repack m16n8 accumulators (tiles 2ks, 2ks+1) into the A-fragment for k-block ks
#define PACK_A(dst, src, ks) do { \
    dst[0] = bf2x(src[2*(ks)][0],   src[2*(ks)][1]); \
    dst[1] = bf2x(src[2*(ks)][2],   src[2*(ks)][3]); \
    dst[2] = bf2x(src[2*(ks)+1][0], src[2*(ks)+1][1]); \
    dst[3] = bf2x(src[2*(ks)+1][2], src[2*(ks)+1][3]); \
} while (0)

// ---------- scratch ----------
__device__ float g_x1   [(size_t)N_NODES * CONV];
__device__ float g_xksig[(size_t)N_NODES * CONV];
__device__ __align__(16) __nv_bfloat16 g_cst2h[(size_t)N_EDGES * NORB * CONV];
__device__ float g_lraw [(size_t)N_EDGES * CONV];
__device__ float g_tbw  [(size_t)N_EDGES * CONV];
__device__ float g_agg  [(size_t)N_NODES * CONV];
__device__ __align__(16) __nv_bfloat16 g_w1h[4096];   // W1^T bf16, [n][k]
__device__ __align__(16) __nv_bfloat16 g_w2h[4096];   // W2^T bf16, [n][k]

// ---------- prep: W (in,out) -> W^T [n][k] bf16 ----------
__global__ void k_prepw(const float* __restrict__ W1, const float* __restrict__ W2) {
    for (int i = threadIdx.x; i < 4096; i += 256) {
        int n = i >> 6, k = i & 63;
        g_w1h[i] = __float2bfloat16(W1[k * 64 + n]);
        g_w2h[i] = __float2bfloat16(W2[k * 64 + n]);
    }
}

// ---------- K1: node transform, 4 nodes/block (also zeroes g_agg) ----------
__global__ void __launch_bounds__(128) k_node(const float* __restrict__ x,
                                              const float* __restrict__ Wn,
                                              const float* __restrict__ bn) {
    __shared__ float xs[4][EMB];
    int n0 = blockIdx.x * 4, j = threadIdx.x;
    if (j < 64)
        ((float4*)g_agg)[(size_t)blockIdx.x * 64 + j] = make_float4(0.f, 0.f, 0.f, 0.f);
#pragma unroll
    for (int v = 0; v < 4; v++)
        xs[v][j] = x[(size_t)(n0 + v) * EMB + j];
    __syncthreads();
    float a0 = bn[j], a1 = a0, a2 = a0, a3 = a0;
#pragma unroll 4
    for (int k = 0; k < EMB; k++) {
        float w = Wn[k * EMB + j];
        a0 = fmaf(xs[0][k], w, a0);
        a1 = fmaf(xs[1][k], w, a1);
        a2 = fmaf(xs[2][k], w, a2);
        a3 = fmaf(xs[3][k], w, a3);
    }
    if (j < CONV) {
        g_x1[(size_t)(n0 + 0) * CONV + j] = a0;
        g_x1[(size_t)(n0 + 1) * CONV + j] = a1;
        g_x1[(size_t)(n0 + 2) * CONV + j] = a2;
        g_x1[(size_t)(n0 + 3) * CONV + j] = a3;
    } else {
        int jj = j - CONV;
        g_xksig[(size_t)(n0 + 0) * CONV + jj] = sigmoid_f(a0);
        g_xksig[(size_t)(n0 + 1) * CONV + jj] = sigmoid_f(a1);
        g_xksig[(size_t)(n0 + 2) * CONV + jj] = sigmoid_f(a2);
        g_xksig[(size_t)(n0 + 3) * CONV + jj] = sigmoid_f(a3);
    }
}

// ---------- K2: bf16 mma double GEMM, register-chained stages (also zeroes g_tbw) ----------
#define LDB 72
#define CST_SMEM_BYTES ((128 * LDB + 2 * 64 * LDB) * 2)   // 36864 B
__global__ void __launch_bounds__(256, 3) k_cst_mma(const float* __restrict__ A,
                                                    const float* __restrict__ rb) {
    extern __shared__ __align__(16) __nv_bfloat16 sb[];
    __nv_bfloat16* sA  = sb;                   // 128 x 72
    __nv_bfloat16* sW1 = sb + 128 * LDB;       // 64 x 72
    __nv_bfloat16* sW2 = sW1 + 64 * LDB;
    const uint32_t sAu  = smem_u32(sA);
    const uint32_t sW1u = smem_u32(sW1);
    const uint32_t sW2u = smem_u32(sW2);

    const int tid = threadIdx.x, wid = tid >> 5, lane = tid & 31;
    const int g = lane >> 2, tg = lane & 3;
    const int wr0 = wid * 16;

    // zero g_tbw for this block's 8 edges (consumed after k_tri)
    if (tid < 128)
        ((float4*)g_tbw)[(size_t)blockIdx.x * 128 + tid] = make_float4(0.f, 0.f, 0.f, 0.f);

    for (int i = tid; i < 512; i += 256) {
        int n = i >> 3, kc = i & 7;
        *(uint4*)(sW1 + n * LDB + kc * 8) = ((const uint4*)g_w1h)[i];
        *(uint4*)(sW2 + n * LDB + kc * 8) = ((const uint4*)g_w2h)[i];
    }
    const float4* Ag = (const float4*)(A + (size_t)blockIdx.x * (128 * 64));
    for (int i = tid; i < 2048; i += 256) {
        int r = i >> 4, c4 = i & 15;
        float4 v = Ag[i];
        *(uint2*)(sA + r * LDB + c4 * 4) = make_uint2(bf2x(v.x, v.y), bf2x(v.z, v.w));
    }
    __syncthreads();

    const uint32_t a_off = A_OFF(lane, LDB);
    const uint32_t b_off = B_OFF(lane, LDB);

    float acc[8][4];
    uint32_t a[4];

    // ---- stage 1: Y = A @ W1 ----
#pragma unroll
    for (int at = 0; at < 8; at++)
#pragma unroll
        for (int q = 0; q < 4; q++) acc[at][q] = 0.f;
#pragma unroll
    for (int ks = 0; ks < 4; ks++) {
        const int k0 = ks * 16;
        ldmx4(a[0], a[1], a[2], a[3], sAu + a_off + (uint32_t)(wr0 * LDB + k0) * 2);
#pragma unroll
        for (int np = 0; np < 4; np++) {
            uint32_t b0, b1, b2, b3;
            ldmx4(b0, b1, b2, b3, sW1u + b_off + (uint32_t)(np * 16 * LDB + k0) * 2);
            mma_bf16(acc[2 * np],     a, b0, b1);
            mma_bf16(acc[2 * np + 1], a, b2, b3);
        }
    }
    // silu + repack accumulators into stage-2 A fragments (register-direct)
    uint32_t aa[4][4];
#pragma unroll
    for (int at = 0; at < 8; at++)
#pragma unroll
        for (int q = 0; q < 4; q++) acc[at][q] = silu_f(acc[at][q]);
#pragma unroll
    for (int ks = 0; ks < 4; ks++) PACK_A(aa[ks], acc, ks);

    // ---- stage 2: Z = silu(Y) @ W2 ----
#pragma unroll
    for (int at = 0; at < 8; at++)
#pragma unroll
        for (int q = 0; q < 4; q++) acc[at][q] = 0.f;
#pragma unroll
    for (int ks = 0; ks < 4; ks++) {
        const int k0 = ks * 16;
#pragma unroll
        for (int np = 0; np < 4; np++) {
            uint32_t b0, b1, b2, b3;
            ldmx4(b0, b1, b2, b3, sW2u + b_off + (uint32_t)(np * 16 * LDB + k0) * 2);
            mma_bf16(acc[2 * np],     aa[ks], b0, b1);
            mma_bf16(acc[2 * np + 1], aa[ks], b2, b3);
        }
    }

    // ---- epilogue: silu, lraw, bf16 store via sA ----
    {
        const int edge = blockIdx.x * 8 + wid;
        float rbl = (lane < NORB) ? rb[(size_t)edge * NORB + lane] : 0.f;
        float rbg  = __shfl_sync(0xffffffffu, rbl, g);
        float rbg8 = __shfl_sync(0xffffffffu, rbl, g + 8);
#pragma unroll
        for (int at = 0; at < 8; at++) {
            float v0 = silu_f(acc[at][0]);
            float v1 = silu_f(acc[at][1]);
            float v2 = silu_f(acc[at][2]);
            float v3 = silu_f(acc[at][3]);
            int c = at * 8 + 2 * tg;
            *(unsigned*)(sA + (wr0 + g) * LDB + c)     = bf2x(v0, v1);
            *(unsigned*)(sA + (wr0 + g + 8) * LDB + c) = bf2x(v2, v3);
            float c0 = rbg * v0 + rbg8 * v2;
            float c1 = rbg * v1 + rbg8 * v3;
#pragma unroll
            for (int o = 4; o < 32; o <<= 1) {
                c0 += __shfl_xor_sync(0xffffffffu, c0, o);
                c1 += __shfl_xor_sync(0xffffffffu, c1, o);
            }
            if (lane < 4)
                *(float2*)&g_lraw[(size_t)edge * CONV + at * 8 + 2 * tg] =
                    make_float2(c0, c1);
        }
    }
    __syncwarp();
    {
        int r = wr0 + (lane >> 1);
        int j0 = (lane & 1) * 4;
        size_t grow = (size_t)blockIdx.x * 128 + r;
        uint4* dst = (uint4*)(g_cst2h + grow * 64);
        const __nv_bfloat16* src = sA + r * LDB;
#pragma unroll
        for (int j = 0; j < 4; j++)
            dst[j0 + j] = *(const uint4*)(src + (j0 + j) * 8);
    }
}

// ---------- K3: triplet kernel ----------
__global__ void __launch_bounds__(256) k_tri(const float* __restrict__ rb,
                                             const float* __restrict__ shb,
                                             const int*   __restrict__ tri_k,
                                             const int*   __restrict__ eks,
                                             const int*   __restrict__ est) {
    int t = (blockIdx.x * blockDim.x + threadIdx.x) >> 5;
    int lane = threadIdx.x & 31;
    if (t >= N_TRI) return;
    int e = eks[t], knode = tri_k[t], eo = est[t];

    float cl = (lane < NORB) ? rb[(size_t)e * NORB + lane] * shb[(size_t)t * NORB + lane] : 0.f;

    const __nv_bfloat162* C = (const __nv_bfloat162*)(g_cst2h + (size_t)e * (NORB * CONV));
    float a0 = 0.f, a1 = 0.f;
#pragma unroll
    for (int d = 0; d < NORB; d++) {
        float c = __shfl_sync(0xffffffffu, cl, d);
        float2 v = __bfloat1622float2(C[d * 32 + lane]);
        a0 = fmaf(c, v.x, a0);
        a1 = fmaf(c, v.y, a1);
    }
    float ss = a0 * a0 + a1 * a1;
#pragma unroll
    for (int o = 16; o; o >>= 1) ss += __shfl_xor_sync(0xffffffffu, ss, o);
    float inv = 1.f / fmaxf(sqrtf(ss), 1e-12f);

    float2 sg = *(const float2*)(g_xksig + (size_t)knode * CONV + 2 * lane);
    red2(&g_tbw[(size_t)eo * CONV + 2 * lane], a0 * inv * sg.x, a1 * inv * sg.y);
}

// ---------- K4: bf16 mma edge kernel, register-chained GEMMs ----------
#define E_W3   0
#define E_WB   4608
#define E_WN2  9216
#define E_WN1  13824
#define E_TW   22528
#define E_CAT  31744
#define E_END  49152
#define LDC    136
#define EDGE_SMEM_BYTES (E_END * 2 + 512 + 1024)
__global__ void __launch_bounds__(256, 2) k_edge(const int* __restrict__ idx_s,
                                                 const int* __restrict__ idx_t,
                                                 const float* __restrict__ W3g,
                                                 const float* __restrict__ Wbg,
                                                 const float* __restrict__ Wn1g,
                                                 const float* __restrict__ bn1g,
                                                 const float* __restrict__ Wn2g,
                                                 const float* __restrict__ bn2g) {
    extern __shared__ __align__(16) __nv_bfloat16 sb[];
    __nv_bfloat16* sW3  = sb + E_W3;
    __nv_bfloat16* sWB  = sb + E_WB;
    __nv_bfloat16* sWN2 = sb + E_WN2;
    __nv_bfloat16* sWN1 = sb + E_WN1;
    __nv_bfloat16* sTW  = sb + E_TW;
    __nv_bfloat16* sCAT = sb + E_CAT;
    float* b1s = (float*)(sb + E_END);
    float* b2s = b1s + 64;
    int*   es  = (int*)(b2s + 64);
    int*   et  = es + 128;
    const uint32_t sW3u  = smem_u32(sW3);
    const uint32_t sWBu  = smem_u32(sWB);
    const uint32_t sWN2u = smem_u32(sWN2);
    const uint32_t sWN1u = smem_u32(sWN1);
    const uint32_t sTWu  = smem_u32(sTW);
    const uint32_t sCATu = smem_u32(sCAT);

    const int tid = threadIdx.x, wid = tid >> 5, lane = tid & 31;
    const int g = lane >> 2, tg = lane & 3;
    const int wr0 = wid * 16;
    const int e0 = blockIdx.x * 128;

    for (int i = tid; i < 4096; i += 256) {
        int k = i >> 6, n = i & 63;
        sW3 [n * LDB + k] = __float2bfloat16(W3g[i]);
        sWB [n * LDB + k] = __float2bfloat16(Wbg[i]);
        sWN2[n * LDB + k] = __float2bfloat16(Wn2g[i]);
    }
    for (int i = tid; i < 8192; i += 256) {
        int k = i >> 6, n = i & 63;
        sWN1[n * LDC + k] = __float2bfloat16(Wn1g[i]);
    }
    if (tid < 64) { b1s[tid] = bn1g[tid]; b2s[tid] = bn2g[tid]; }
    if (tid < 128) {
        int e = e0 + tid;
        es[tid] = (e < N_EDGES) ? idx_s[e] : 0;
        et[tid] = (e < N_EDGES) ? idx_t[e] : 0;
    }
    for (int i = tid; i < 2048; i += 256) {
        int r = i >> 4, c4 = i & 15;
        float4 v = (e0 + r < N_EDGES) ? ((const float4*)g_tbw)[(size_t)(e0 + r) * 16 + c4]
                                      : make_float4(0.f, 0.f, 0.f, 0.f);
        *(uint2*)(sTW + r * LDB + c4 * 4) = make_uint2(bf2x(v.x, v.y), bf2x(v.z, v.w));
    }
    __syncthreads();

    for (int i = tid; i < 4096; i += 256) {
        int r = i >> 5, c4 = i & 31;
        int node = (c4 < 16) ? es[r] : et[r];
        float4 v = (e0 + r < N_EDGES) ? ((const float4*)g_x1)[(size_t)node * 16 + (c4 & 15)]
                                      : make_float4(0.f, 0.f, 0.f, 0.f);
        *(uint2*)(sCAT + r * LDC + c4 * 4) = make_uint2(bf2x(v.x, v.y), bf2x(v.z, v.w));
    }
    __syncthreads();

    const uint32_t a_offB = A_OFF(lane, LDB);
    const uint32_t b_offB = B_OFF(lane, LDB);
    const uint32_t a_offC = A_OFF(lane, LDC);
    const uint32_t b_offC = B_OFF(lane, LDC);

    float acc[8][4];
    uint32_t a[4];
    uint32_t la[4][4];   // lc A-fragments
    uint32_t na[4][4];   // n1 A-fragments

    // ---- GEMM1: proj = tw @ W3 -> lc (normalize in regs, pack) ----
#pragma unroll
    for (int at = 0; at < 8; at++)
#pragma unroll
        for (int q = 0; q < 4; q++) acc[at][q] = 0.f;
#pragma unroll
    for (int ks = 0; ks < 4; ks++) {
        const int k0 = ks * 16;
        ldmx4(a[0], a[1], a[2], a[3], sTWu + a_offB + (uint32_t)(wr0 * LDB + k0) * 2);
#pragma unroll
        for (int np = 0; np < 4; np++) {
            uint32_t b0, b1, b2, b3;
            ldmx4(b0, b1, b2, b3, sW3u + b_offB + (uint32_t)(np * 16 * LDB + k0) * 2);
            mma_bf16(acc[2 * np],     a, b0, b1);
            mma_bf16(acc[2 * np + 1], a, b2, b3);
        }
    }
    {
        size_t eg  = (size_t)(e0 + wr0 + g);
        size_t eg8 = eg + 8;
        bool ok0 = eg  < N_EDGES;
        bool ok8 = eg8 < N_EDGES;
        float s0 = 0.f, s8 = 0.f;
#pragma unroll
        for (int at = 0; at < 8; at++) {
            int c = at * 8 + 2 * tg;
            float2 l0 = ok0 ? *(const float2*)&g_lraw[eg * CONV + c]  : make_float2(0.f, 0.f);
            float2 l8 = ok8 ? *(const float2*)&g_lraw[eg8 * CONV + c] : make_float2(0.f, 0.f);
            acc[at][0] = l0.x * (1.f + acc[at][0]);
            acc[at][1] = l0.y * (1.f + acc[at][1]);
            acc[at][2] = l8.x * (1.f + acc[at][2]);
            acc[at][3] = l8.y * (1.f + acc[at][3]);
            s0 += acc[at][0] * acc[at][0] + acc[at][1] * acc[at][1];
            s8 += acc[at][2] * acc[at][2] + acc[at][3] * acc[at][3];
        }
#pragma unroll
        for (int o = 1; o < 4; o <<= 1) {
            s0 += __shfl_xor_sync(0xffffffffu, s0, o);
            s8 += __shfl_xor_sync(0xffffffffu, s8, o);
        }
        float i0 = 1.f / fmaxf(sqrtf(s0), 1e-12f);
        float i8 = 1.f / fmaxf(sqrtf(s8), 1e-12f);
#pragma unroll
        for (int at = 0; at < 8; at++) {
            acc[at][0] *= i0; acc[at][1] *= i0;
            acc[at][2] *= i8; acc[at][3] *= i8;
        }
#pragma unroll
        for (int ks = 0; ks < 4; ks++) PACK_A(la[ks], acc, ks);
    }

    // ---- GEMM2: n1 = silu(cat @ Wn1 + b1) -> pack ----
#pragma unroll
    for (int at = 0; at < 8; at++) {
        int c = at * 8 + 2 * tg;
        acc[at][0] = b1s[c]; acc[at][1] = b1s[c + 1];
        acc[at][2] = acc[at][0]; acc[at][3] = acc[at][1];
    }
#pragma unroll
    for (int ks = 0; ks < 8; ks++) {
        const int k0 = ks * 16;
        ldmx4(a[0], a[1], a[2], a[3], sCATu + a_offC + (uint32_t)(wr0 * LDC + k0) * 2);
#pragma unroll
        for (int np = 0; np < 4; np++) {
            uint32_t b0, b1, b2, b3;
            ldmx4(b0, b1, b2, b3, sWN1u + b_offC + (uint32_t)(np * 16 * LDC + k0) * 2);
            mma_bf16(acc[2 * np],     a, b0, b1);
            mma_bf16(acc[2 * np + 1], a, b2, b3);
        }
    }
#pragma unroll
    for (int at = 0; at < 8; at++)
#pragma unroll
        for (int q = 0; q < 4; q++) acc[at][q] = silu_f(acc[at][q]);
#pragma unroll
    for (int ks = 0; ks < 4; ks++) PACK_A(na[ks], acc, ks);

    // ---- GEMM3: nf = silu(n1 @ Wn2 + b2) (regs) ----
    float nf[8][4];
#pragma unroll
    for (int at = 0; at < 8; at++) {
        int c = at * 8 + 2 * tg;
        nf[at][0] = b2s[c]; nf[at][1] = b2s[c + 1];
        nf[at][2] = nf[at][0]; nf[at][3] = nf[at][1];
    }
#pragma unroll
    for (int ks = 0; ks < 4; ks++) {
        const int k0 = ks * 16;
#pragma unroll
        for (int np = 0; np < 4; np++) {
            uint32_t b0, b1, b2, b3;
            ldmx4(b0, b1, b2, b3, sWN2u + b_offB + (uint32_t)(np * 16 * LDB + k0) * 2);
            mma_bf16(nf[2 * np],     na[ks], b0, b1);
            mma_bf16(nf[2 * np + 1], na[ks], b2, b3);
        }
    }
#pragma unroll
    for (int at = 0; at < 8; at++)
#pragma unroll
        for (int q = 0; q < 4; q++) nf[at][q] = silu_f(nf[at][q]);

    // ---- GEMM4: m = lc @ Wb ----
#pragma unroll
    for (int at = 0; at < 8; at++)
#pragma unroll
        for (int q = 0; q < 4; q++) acc[at][q] = 0.f;
#pragma unroll
    for (int ks = 0; ks < 4; ks++) {
        const int k0 = ks * 16;
#pragma unroll
        for (int np = 0; np < 4; np++) {
            uint32_t b0, b1, b2, b3;
            ldmx4(b0, b1, b2, b3, sWBu + b_offB + (uint32_t)(np * 16 * LDB + k0) * 2);
            mma_bf16(acc[2 * np],     la[ks], b0, b1);
            mma_bf16(acc[2 * np + 1], la[ks], b2, b3);
        }
    }

    // ---- scatter msg = m * nf by idx_s ----
    {
        int rg = wr0 + g;
        int ns0 = es[rg], ns8 = es[rg + 8];
        bool ok0 = (e0 + rg) < N_EDGES;
        bool ok8 = (e0 + rg + 8) < N_EDGES;
#pragma unroll
        for (int at = 0; at < 8; at++) {
            int c = at * 8 + 2 * tg;
            if (ok0) red2(&g_agg[(size_t)ns0 * CONV + c],
                          acc[at][0] * nf[at][0], acc[at][1] * nf[at][1]);
            if (ok8) red2(&g_agg[(size_t)ns8 * CONV + c],
                          acc[at][2] * nf[at][2], acc[at][3] * nf[at][3]);
        }
    }
}

// ---------- K5: out = x + agg @ W_out, 4 nodes/block ----------
__global__ void __launch_bounds__(128) k_out(const float* __restrict__ x,
                                             const float* __restrict__ Wout,
                                             float* __restrict__ out) {
    __shared__ float ags[4][CONV];
    int n0 = blockIdx.x * 4, j = threadIdx.x;
    if (j < 2 * CONV) {
        int v = j >> 6, c = j & 63;
        ags[v][c]     = g_agg[(size_t)(n0 + v) * CONV + c];
        ags[v + 2][c] = g_agg[(size_t)(n0 + v + 2) * CONV + c];
    }
    __syncthreads();
    float a0 = 0.f, a1 = 0.f, a2 = 0.f, a3 = 0.f;
#pragma unroll 4
    for (int k = 0; k < CONV; k++) {
        float w = Wout[k * EMB + j];
        a0 = fmaf(ags[0][k], w, a0);
        a1 = fmaf(ags[1][k], w, a1);
        a2 = fmaf(ags[2][k], w, a2);
        a3 = fmaf(ags[3][k], w, a3);
    }
    out[(size_t)(n0 + 0) * EMB + j] = x[(size_t)(n0 + 0) * EMB + j] + a0;
    out[(size_t)(n0 + 1) * EMB + j] = x[(size_t)(n0 + 1) * EMB + j] + a1;
    out[(size_t)(n0 + 2) * EMB + j] = x[(size_t)(n0 + 2) * EMB + j] + a2;
    out[(size_t)(n0 + 3) * EMB + j] = x[(size_t)(n0 + 3) * EMB + j] + a3;
}

extern "C" void kernel_launch(void* const* d_in, const int* in_sizes, int n_in,
                              void* d_out, int out_size) {
    const float* x      = (const float*)d_in[0];
    const float* cst    = (const float*)d_in[1];
    const float* rb     = (const float*)d_in[2];
    const float* shb    = (const float*)d_in[3];
    const int*   idx_s  = (const int*)  d_in[4];
    const int*   idx_t  = (const int*)  d_in[5];
    const int*   tri_k  = (const int*)  d_in[6];
    const int*   eks    = (const int*)  d_in[7];
    const int*   est    = (const int*)  d_in[8];
    const float* W_node = (const float*)d_in[9];
    const float* b_node = (const float*)d_in[10];
    const float* W_c1   = (const float*)d_in[11];
    const float* W_c2   = (const float*)d_in[12];
    const float* W_three= (const float*)d_in[13];
    const float* W_basis= (const float*)d_in[14];
    const float* W_n1   = (const float*)d_in[15];
    const float* b_n1   = (const float*)d_in[16];
    const float* W_n2   = (const float*)d_in[17];
    const float* b_n2   = (const float*)d_in[18];
    const float* W_out  = (const float*)d_in[19];
    float* out = (float*)d_out;

    cudaFuncSetAttribute(k_edge,    cudaFuncAttributeMaxDynamicSharedMemorySize, EDGE_SMEM_BYTES);
    cudaFuncSetAttribute(k_cst_mma, cudaFuncAttributeMaxDynamicSharedMemorySize, CST_SMEM_BYTES);

    k_node<<<N_NODES / 4, 128>>>(x, W_node, b_node);
    k_prepw<<<1, 256>>>(W_c1, W_c2);
    k_cst_mma<<<(N_EDGES * NORB) / 128, 256, CST_SMEM_BYTES>>>(cst, rb);
    k_tri <<<(N_TRI * 32) / 256, 256>>>(rb, shb, tri_k, eks, est);
    k_edge<<<(N_EDGES + 127) / 128, 256, EDGE_SMEM_BYTES>>>(idx_s, idx_t, W_three, W_basis,
                                                            W_n1, b_n1, W_n2, b_n2);
    k_out <<<N_NODES / 4, 128>>>(x, W_out, out);
}

// round 8
// speedup vs baseline: 2.6516x; 1.1994x over previous
#include <cuda_runtime.h>
#include <cuda_bf16.h>
#include <math.h>
#include <stdint.h>

#define N_NODES 20000
#define N_EDGES 100000
#define N_TRI   200000
#define NORB    16
#define EMB     128
#define CONV    64

typedef unsigned long long u64;

__device__ __forceinline__ float tanh_f(float x) {
    float r; asm("tanh.approx.f32 %0, %1;" : "=f"(r) : "f"(x)); return r;
}
// silu(x) = x*sigmoid(x) = h + h*tanh(h), h = x/2   (1 MUFU instead of 2)
__device__ __forceinline__ float silu_f(float x) {
    float h = 0.5f * x;
    return fmaf(h, tanh_f(h), h);
}
__device__ __forceinline__ float sigmoid_f(float x) {
    return fmaf(0.5f, tanh_f(0.5f * x), 0.5f);
}
__device__ __forceinline__ void red2(float* p, float a, float b) {
    asm volatile("red.global.add.v2.f32 [%0], {%1, %2};" :: "l"(p), "f"(a), "f"(b) : "memory");
}
__device__ __forceinline__ uint32_t smem_u32(const void* p) {
    uint32_t a;
    asm("{ .reg .u64 t; cvta.to.shared.u64 t, %1; cvt.u32.u64 %0, t; }" : "=r"(a) : "l"(p));
    return a;
}
__device__ __forceinline__ void mma_bf16(float d[4], const uint32_t a[4],
                                         uint32_t b0, uint32_t b1) {
    asm("mma.sync.aligned.m16n8k16.row.col.f32.bf16.bf16.f32 "
        "{%0,%1,%2,%3}, {%4,%5,%6,%7}, {%8,%9}, {%0,%1,%2,%3};"
        : "+f"(d[0]), "+f"(d[1]), "+f"(d[2]), "+f"(d[3])
        : "r"(a[0]), "r"(a[1]), "r"(a[2]), "r"(a[3]), "r"(b0), "r"(b1));
}
__device__ __forceinline__ void ldmx4(uint32_t &r0, uint32_t &r1, uint32_t &r2,
                                      uint32_t &r3, uint32_t addr) {
    asm volatile("ldmatrix.sync.aligned.m8n8.x4.shared.b16 {%0,%1,%2,%3}, [%4];"
                 : "=r"(r0), "=r"(r1), "=r"(r2), "=r"(r3) : "r"(addr));
}
__device__ __forceinline__ unsigned bf2x(float lo, float hi) {
    __nv_bfloat162 h = __float22bfloat162_rn(make_float2(lo, hi));
    return *reinterpret_cast<unsigned*>(&h);
}

#define A_OFF(lane, ld) ((uint32_t)(((lane) & 15) * (ld) + (((lane) >> 4) << 3)) * 2u)
#define B_OFF(lane, ld) ((uint32_t)(((((lane) >> 4) << 3) + ((lane) & 7)) * (ld) + \
                                    ((((lane) >> 3) & 1) << 3)) * 2u)
#define PACK_A(dst, src, ks) do { \
    dst[0] = bf2x(src[2*(ks)][0],   src[2*(ks)][1]); \
    dst[1] = bf2x(src[2*(ks)][2],   src[2*(ks)][3]); \
    dst[2] = bf2x(src[2*(ks)+1][0], src[2*(ks)+1][1]); \
    dst[3] = bf2x(src[2*(ks)+1][2], src[2*(ks)+1][3]); \
} while (0)

// ---------- scratch ----------
__device__ float g_x1   [(size_t)N_NODES * CONV];
__device__ float g_xksig[(size_t)N_NODES * CONV];
__device__ __align__(16) __nv_bfloat16 g_cst2h[(size_t)N_EDGES * NORB * CONV];
__device__ float g_lraw [(size_t)N_EDGES * CONV];
__device__ float g_tbw  [(size_t)N_EDGES * CONV];
__device__ float g_agg  [(size_t)N_NODES * CONV];
__device__ __align__(16) __nv_bfloat16 g_w1h[4096];
__device__ __align__(16) __nv_bfloat16 g_w2h[4096];

// ---------- prep: W (in,out) -> W^T [n][k] bf16 ----------
__global__ void k_prepw(const float* __restrict__ W1, const float* __restrict__ W2) {
    for (int i = threadIdx.x; i < 4096; i += 256) {
        int n = i >> 6, k = i & 63;
        g_w1h[i] = __float2bfloat16(W1[k * 64 + n]);
        g_w2h[i] = __float2bfloat16(W2[k * 64 + n]);
    }
}

// ---------- K1: node transform, 4 nodes/block (also zeroes g_agg) ----------
__global__ void __launch_bounds__(128) k_node(const float* __restrict__ x,
                                              const float* __restrict__ Wn,
                                              const float* __restrict__ bn) {
    __shared__ float xs[4][EMB];
    int n0 = blockIdx.x * 4, j = threadIdx.x;
    if (j < 64)
        ((float4*)g_agg)[(size_t)blockIdx.x * 64 + j] = make_float4(0.f, 0.f, 0.f, 0.f);
#pragma unroll
    for (int v = 0; v < 4; v++)
        xs[v][j] = x[(size_t)(n0 + v) * EMB + j];
    __syncthreads();
    float a0 = bn[j], a1 = a0, a2 = a0, a3 = a0;
#pragma unroll 4
    for (int k = 0; k < EMB; k++) {
        float w = Wn[k * EMB + j];
        a0 = fmaf(xs[0][k], w, a0);
        a1 = fmaf(xs[1][k], w, a1);
        a2 = fmaf(xs[2][k], w, a2);
        a3 = fmaf(xs[3][k], w, a3);
    }
    if (j < CONV) {
        g_x1[(size_t)(n0 + 0) * CONV + j] = a0;
        g_x1[(size_t)(n0 + 1) * CONV + j] = a1;
        g_x1[(size_t)(n0 + 2) * CONV + j] = a2;
        g_x1[(size_t)(n0 + 3) * CONV + j] = a3;
    } else {
        int jj = j - CONV;
        g_xksig[(size_t)(n0 + 0) * CONV + jj] = sigmoid_f(a0);
        g_xksig[(size_t)(n0 + 1) * CONV + jj] = sigmoid_f(a1);
        g_xksig[(size_t)(n0 + 2) * CONV + jj] = sigmoid_f(a2);
        g_xksig[(size_t)(n0 + 3) * CONV + jj] = sigmoid_f(a3);
    }
}

// ---------- K2: bf16 mma double GEMM, register-chained (also zeroes g_tbw) ----------
#define LDB 72
#define CST_SMEM_BYTES ((128 * LDB + 2 * 64 * LDB) * 2)
__global__ void __launch_bounds__(256, 3) k_cst_mma(const float* __restrict__ A,
                                                    const float* __restrict__ rb) {
    extern __shared__ __align__(16) __nv_bfloat16 sb[];
    __nv_bfloat16* sA  = sb;
    __nv_bfloat16* sW1 = sb + 128 * LDB;
    __nv_bfloat16* sW2 = sW1 + 64 * LDB;
    const uint32_t sAu  = smem_u32(sA);
    const uint32_t sW1u = smem_u32(sW1);
    const uint32_t sW2u = smem_u32(sW2);

    const int tid = threadIdx.x, wid = tid >> 5, lane = tid & 31;
    const int g = lane >> 2, tg = lane & 3;
    const int wr0 = wid * 16;

    if (tid < 128)
        ((float4*)g_tbw)[(size_t)blockIdx.x * 128 + tid] = make_float4(0.f, 0.f, 0.f, 0.f);

    for (int i = tid; i < 512; i += 256) {
        int n = i >> 3, kc = i & 7;
        *(uint4*)(sW1 + n * LDB + kc * 8) = ((const uint4*)g_w1h)[i];
        *(uint4*)(sW2 + n * LDB + kc * 8) = ((const uint4*)g_w2h)[i];
    }
    const float4* Ag = (const float4*)(A + (size_t)blockIdx.x * (128 * 64));
    for (int i = tid; i < 2048; i += 256) {
        int r = i >> 4, c4 = i & 15;
        float4 v = Ag[i];
        *(uint2*)(sA + r * LDB + c4 * 4) = make_uint2(bf2x(v.x, v.y), bf2x(v.z, v.w));
    }
    __syncthreads();

    const uint32_t a_off = A_OFF(lane, LDB);
    const uint32_t b_off = B_OFF(lane, LDB);

    float acc[8][4];
    uint32_t a[4];

    // ---- stage 1: Y = A @ W1 ----
#pragma unroll
    for (int at = 0; at < 8; at++)
#pragma unroll
        for (int q = 0; q < 4; q++) acc[at][q] = 0.f;
#pragma unroll
    for (int ks = 0; ks < 4; ks++) {
        const int k0 = ks * 16;
        ldmx4(a[0], a[1], a[2], a[3], sAu + a_off + (uint32_t)(wr0 * LDB + k0) * 2);
#pragma unroll
        for (int np = 0; np < 4; np++) {
            uint32_t b0, b1, b2, b3;
            ldmx4(b0, b1, b2, b3, sW1u + b_off + (uint32_t)(np * 16 * LDB + k0) * 2);
            mma_bf16(acc[2 * np],     a, b0, b1);
            mma_bf16(acc[2 * np + 1], a, b2, b3);
        }
    }
    uint32_t aa[4][4];
#pragma unroll
    for (int at = 0; at < 8; at++)
#pragma unroll
        for (int q = 0; q < 4; q++) acc[at][q] = silu_f(acc[at][q]);
#pragma unroll
    for (int ks = 0; ks < 4; ks++) PACK_A(aa[ks], acc, ks);

    // ---- stage 2: Z = silu(Y) @ W2 ----
#pragma unroll
    for (int at = 0; at < 8; at++)
#pragma unroll
        for (int q = 0; q < 4; q++) acc[at][q] = 0.f;
#pragma unroll
    for (int ks = 0; ks < 4; ks++) {
        const int k0 = ks * 16;
#pragma unroll
        for (int np = 0; np < 4; np++) {
            uint32_t b0, b1, b2, b3;
            ldmx4(b0, b1, b2, b3, sW2u + b_off + (uint32_t)(np * 16 * LDB + k0) * 2);
            mma_bf16(acc[2 * np],     aa[ks], b0, b1);
            mma_bf16(acc[2 * np + 1], aa[ks], b2, b3);
        }
    }

    // ---- epilogue: silu, lraw, bf16 store via sA ----
    {
        const int edge = blockIdx.x * 8 + wid;
        float rbl = (lane < NORB) ? rb[(size_t)edge * NORB + lane] : 0.f;
        float rbg  = __shfl_sync(0xffffffffu, rbl, g);
        float rbg8 = __shfl_sync(0xffffffffu, rbl, g + 8);
#pragma unroll
        for (int at = 0; at < 8; at++) {
            float v0 = silu_f(acc[at][0]);
            float v1 = silu_f(acc[at][1]);
            float v2 = silu_f(acc[at][2]);
            float v3 = silu_f(acc[at][3]);
            int c = at * 8 + 2 * tg;
            *(unsigned*)(sA + (wr0 + g) * LDB + c)     = bf2x(v0, v1);
            *(unsigned*)(sA + (wr0 + g + 8) * LDB + c) = bf2x(v2, v3);
            float c0 = rbg * v0 + rbg8 * v2;
            float c1 = rbg * v1 + rbg8 * v3;
#pragma unroll
            for (int o = 4; o < 32; o <<= 1) {
                c0 += __shfl_xor_sync(0xffffffffu, c0, o);
                c1 += __shfl_xor_sync(0xffffffffu, c1, o);
            }
            if (lane < 4)
                *(float2*)&g_lraw[(size_t)edge * CONV + at * 8 + 2 * tg] =
                    make_float2(c0, c1);
        }
    }
    __syncwarp();
    {
        int r = wr0 + (lane >> 1);
        int j0 = (lane & 1) * 4;
        size_t grow = (size_t)blockIdx.x * 128 + r;
        uint4* dst = (uint4*)(g_cst2h + grow * 64);
        const __nv_bfloat16* src = sA + r * LDB;
#pragma unroll
        for (int j = 0; j < 4; j++)
            dst[j0 + j] = *(const uint4*)(src + (j0 + j) * 8);
    }
}

// ---------- K3: triplet kernel ----------
__global__ void __launch_bounds__(256) k_tri(const float* __restrict__ rb,
                                             const float* __restrict__ shb,
                                             const int*   __restrict__ tri_k,
                                             const int*   __restrict__ eks,
                                             const int*   __restrict__ est) {
    int t = (blockIdx.x * blockDim.x + threadIdx.x) >> 5;
    int lane = threadIdx.x & 31;
    if (t >= N_TRI) return;
    int e = eks[t], knode = tri_k[t], eo = est[t];

    float cl = (lane < NORB) ? rb[(size_t)e * NORB + lane] * shb[(size_t)t * NORB + lane] : 0.f;

    const __nv_bfloat162* C = (const __nv_bfloat162*)(g_cst2h + (size_t)e * (NORB * CONV));
    float a0 = 0.f, a1 = 0.f;
#pragma unroll
    for (int d = 0; d < NORB; d++) {
        float c = __shfl_sync(0xffffffffu, cl, d);
        float2 v = __bfloat1622float2(C[d * 32 + lane]);
        a0 = fmaf(c, v.x, a0);
        a1 = fmaf(c, v.y, a1);
    }
    float ss = a0 * a0 + a1 * a1;
#pragma unroll
    for (int o = 16; o; o >>= 1) ss += __shfl_xor_sync(0xffffffffu, ss, o);
    float inv = 1.f / fmaxf(sqrtf(ss), 1e-12f);

    float2 sg = *(const float2*)(g_xksig + (size_t)knode * CONV + 2 * lane);
    red2(&g_tbw[(size_t)eo * CONV + 2 * lane], a0 * inv * sg.x, a1 * inv * sg.y);
}

// ---------- K4: bf16 mma edge kernel, register-chained GEMMs ----------
#define E_W3   0
#define E_WB   4608
#define E_WN2  9216
#define E_WN1  13824
#define E_TW   22528
#define E_CAT  31744
#define E_END  49152
#define LDC    136
#define EDGE_SMEM_BYTES (E_END * 2 + 512 + 1024)
__global__ void __launch_bounds__(256, 2) k_edge(const int* __restrict__ idx_s,
                                                 const int* __restrict__ idx_t,
                                                 const float* __restrict__ W3g,
                                                 const float* __restrict__ Wbg,
                                                 const float* __restrict__ Wn1g,
                                                 const float* __restrict__ bn1g,
                                                 const float* __restrict__ Wn2g,
                                                 const float* __restrict__ bn2g) {
    extern __shared__ __align__(16) __nv_bfloat16 sb[];
    __nv_bfloat16* sW3  = sb + E_W3;
    __nv_bfloat16* sWB  = sb + E_WB;
    __nv_bfloat16* sWN2 = sb + E_WN2;
    __nv_bfloat16* sWN1 = sb + E_WN1;
    __nv_bfloat16* sTW  = sb + E_TW;
    __nv_bfloat16* sCAT = sb + E_CAT;
    float* b1s = (float*)(sb + E_END);
    float* b2s = b1s + 64;
    int*   es  = (int*)(b2s + 64);
    int*   et  = es + 128;
    const uint32_t sW3u  = smem_u32(sW3);
    const uint32_t sWBu  = smem_u32(sWB);
    const uint32_t sWN2u = smem_u32(sWN2);
    const uint32_t sWN1u = smem_u32(sWN1);
    const uint32_t sTWu  = smem_u32(sTW);
    const uint32_t sCATu = smem_u32(sCAT);

    const int tid = threadIdx.x, wid = tid >> 5, lane = tid & 31;
    const int g = lane >> 2, tg = lane & 3;
    const int wr0 = wid * 16;
    const int e0 = blockIdx.x * 128;

    for (int i = tid; i < 4096; i += 256) {
        int k = i >> 6, n = i & 63;
        sW3 [n * LDB + k] = __float2bfloat16(W3g[i]);
        sWB [n * LDB + k] = __float2bfloat16(Wbg[i]);
        sWN2[n * LDB + k] = __float2bfloat16(Wn2g[i]);
    }
    for (int i = tid; i < 8192; i += 256) {
        int k = i >> 6, n = i & 63;
        sWN1[n * LDC + k] = __float2bfloat16(Wn1g[i]);
    }
    if (tid < 64) { b1s[tid] = bn1g[tid]; b2s[tid] = bn2g[tid]; }
    if (tid < 128) {
        int e = e0 + tid;
        es[tid] = (e < N_EDGES) ? idx_s[e] : 0;
        et[tid] = (e < N_EDGES) ? idx_t[e] : 0;
    }
    for (int i = tid; i < 2048; i += 256) {
        int r = i >> 4, c4 = i & 15;
        float4 v = (e0 + r < N_EDGES) ? ((const float4*)g_tbw)[(size_t)(e0 + r) * 16 + c4]
                                      : make_float4(0.f, 0.f, 0.f, 0.f);
        *(uint2*)(sTW + r * LDB + c4 * 4) = make_uint2(bf2x(v.x, v.y), bf2x(v.z, v.w));
    }
    __syncthreads();

    for (int i = tid; i < 4096; i += 256) {
        int r = i >> 5, c4 = i & 31;
        int node = (c4 < 16) ? es[r] : et[r];
        float4 v = (e0 + r < N_EDGES) ? ((const float4*)g_x1)[(size_t)node * 16 + (c4 & 15)]
                                      : make_float4(0.f, 0.f, 0.f, 0.f);
        *(uint2*)(sCAT + r * LDC + c4 * 4) = make_uint2(bf2x(v.x, v.y), bf2x(v.z, v.w));
    }
    __syncthreads();

    const uint32_t a_offB = A_OFF(lane, LDB);
    const uint32_t b_offB = B_OFF(lane, LDB);
    const uint32_t a_offC = A_OFF(lane, LDC);
    const uint32_t b_offC = B_OFF(lane, LDC);

    float acc[8][4];
    uint32_t a[4];
    uint32_t la[4][4];
    uint32_t na[4][4];

    // ---- GEMM1: proj = tw @ W3 -> lc ----
#pragma unroll
    for (int at = 0; at < 8; at++)
#pragma unroll
        for (int q = 0; q < 4; q++) acc[at][q] = 0.f;
#pragma unroll
    for (int ks = 0; ks < 4; ks++) {
        const int k0 = ks * 16;
        ldmx4(a[0], a[1], a[2], a[3], sTWu + a_offB + (uint32_t)(wr0 * LDB + k0) * 2);
#pragma unroll
        for (int np = 0; np < 4; np++) {
            uint32_t b0, b1, b2, b3;
            ldmx4(b0, b1, b2, b3, sW3u + b_offB + (uint32_t)(np * 16 * LDB + k0) * 2);
            mma_bf16(acc[2 * np],     a, b0, b1);
            mma_bf16(acc[2 * np + 1], a, b2, b3);
        }
    }
    {
        size_t eg  = (size_t)(e0 + wr0 + g);
        size_t eg8 = eg + 8;
        bool ok0 = eg  < N_EDGES;
        bool ok8 = eg8 < N_EDGES;
        float s0 = 0.f, s8 = 0.f;
#pragma unroll
        for (int at = 0; at < 8; at++) {
            int c = at * 8 + 2 * tg;
            float2 l0 = ok0 ? *(const float2*)&g_lraw[eg * CONV + c]  : make_float2(0.f, 0.f);
            float2 l8 = ok8 ? *(const float2*)&g_lraw[eg8 * CONV + c] : make_float2(0.f, 0.f);
            acc[at][0] = l0.x * (1.f + acc[at][0]);
            acc[at][1] = l0.y * (1.f + acc[at][1]);
            acc[at][2] = l8.x * (1.f + acc[at][2]);
            acc[at][3] = l8.y * (1.f + acc[at][3]);
            s0 += acc[at][0] * acc[at][0] + acc[at][1] * acc[at][1];
            s8 += acc[at][2] * acc[at][2] + acc[at][3] * acc[at][3];
        }
#pragma unroll
        for (int o = 1; o < 4; o <<= 1) {
            s0 += __shfl_xor_sync(0xffffffffu, s0, o);
            s8 += __shfl_xor_sync(0xffffffffu, s8, o);
        }
        float i0 = 1.f / fmaxf(sqrtf(s0), 1e-12f);
        float i8 = 1.f / fmaxf(sqrtf(s8), 1e-12f);
#pragma unroll
        for (int at = 0; at < 8; at++) {
            acc[at][0] *= i0; acc[at][1] *= i0;
            acc[at][2] *= i8; acc[at][3] *= i8;
        }
#pragma unroll
        for (int ks = 0; ks < 4; ks++) PACK_A(la[ks], acc, ks);
    }

    // ---- GEMM2: n1 = silu(cat @ Wn1 + b1) ----
#pragma unroll
    for (int at = 0; at < 8; at++) {
        int c = at * 8 + 2 * tg;
        acc[at][0] = b1s[c]; acc[at][1] = b1s[c + 1];
        acc[at][2] = acc[at][0]; acc[at][3] = acc[at][1];
    }
#pragma unroll
    for (int ks = 0; ks < 8; ks++) {
        const int k0 = ks * 16;
        ldmx4(a[0], a[1], a[2], a[3], sCATu + a_offC + (uint32_t)(wr0 * LDC + k0) * 2);
#pragma unroll
        for (int np = 0; np < 4; np++) {
            uint32_t b0, b1, b2, b3;
            ldmx4(b0, b1, b2, b3, sWN1u + b_offC + (uint32_t)(np * 16 * LDC + k0) * 2);
            mma_bf16(acc[2 * np],     a, b0, b1);
            mma_bf16(acc[2 * np + 1], a, b2, b3);
        }
    }
#pragma unroll
    for (int at = 0; at < 8; at++)
#pragma unroll
        for (int q = 0; q < 4; q++) acc[at][q] = silu_f(acc[at][q]);
#pragma unroll
    for (int ks = 0; ks < 4; ks++) PACK_A(na[ks], acc, ks);

    // ---- GEMM3: nf = silu(n1 @ Wn2 + b2) ----
    float nf[8][4];
#pragma unroll
    for (int at = 0; at < 8; at++) {
        int c = at * 8 + 2 * tg;
        nf[at][0] = b2s[c]; nf[at][1] = b2s[c + 1];
        nf[at][2] = nf[at][0]; nf[at][3] = nf[at][1];
    }
#pragma unroll
    for (int ks = 0; ks < 4; ks++) {
        const int k0 = ks * 16;
#pragma unroll
        for (int np = 0; np < 4; np++) {
            uint32_t b0, b1, b2, b3;
            ldmx4(b0, b1, b2, b3, sWN2u + b_offB + (uint32_t)(np * 16 * LDB + k0) * 2);
            mma_bf16(nf[2 * np],     na[ks], b0, b1);
            mma_bf16(nf[2 * np + 1], na[ks], b2, b3);
        }
    }
#pragma unroll
    for (int at = 0; at < 8; at++)
#pragma unroll
        for (int q = 0; q < 4; q++) nf[at][q] = silu_f(nf[at][q]);

    // ---- GEMM4: m = lc @ Wb ----
#pragma unroll
    for (int at = 0; at < 8; at++)
#pragma unroll
        for (int q = 0; q < 4; q++) acc[at][q] = 0.f;
#pragma unroll
    for (int ks = 0; ks < 4; ks++) {
        const int k0 = ks * 16;
#pragma unroll
        for (int np = 0; np < 4; np++) {
            uint32_t b0, b1, b2, b3;
            ldmx4(b0, b1, b2, b3, sWBu + b_offB + (uint32_t)(np * 16 * LDB + k0) * 2);
            mma_bf16(acc[2 * np],     la[ks], b0, b1);
            mma_bf16(acc[2 * np + 1], la[ks], b2, b3);
        }
    }

    // ---- scatter msg = m * nf by idx_s ----
    {
        int rg = wr0 + g;
        int ns0 = es[rg], ns8 = es[rg + 8];
        bool ok0 = (e0 + rg) < N_EDGES;
        bool ok8 = (e0 + rg + 8) < N_EDGES;
#pragma unroll
        for (int at = 0; at < 8; at++) {
            int c = at * 8 + 2 * tg;
            if (ok0) red2(&g_agg[(size_t)ns0 * CONV + c],
                          acc[at][0] * nf[at][0], acc[at][1] * nf[at][1]);
            if (ok8) red2(&g_agg[(size_t)ns8 * CONV + c],
                          acc[at][2] * nf[at][2], acc[at][3] * nf[at][3]);
        }
    }
}

// ---------- K5: out = x + agg @ W_out, 4 nodes/block ----------
__global__ void __launch_bounds__(128) k_out(const float* __restrict__ x,
                                             const float* __restrict__ Wout,
                                             float* __restrict__ out) {
    __shared__ float ags[4][CONV];
    int n0 = blockIdx.x * 4, j = threadIdx.x;
    if (j < 2 * CONV) {
        int v = j >> 6, c = j & 63;
        ags[v][c]     = g_agg[(size_t)(n0 + v) * CONV + c];
        ags[v + 2][c] = g_agg[(size_t)(n0 + v + 2) * CONV + c];
    }
    __syncthreads();
    float a0 = 0.f, a1 = 0.f, a2 = 0.f, a3 = 0.f;
#pragma unroll 4
    for (int k = 0; k < CONV; k++) {
        float w = Wout[k * EMB + j];
        a0 = fmaf(ags[0][k], w, a0);
        a1 = fmaf(ags[1][k], w, a1);
        a2 = fmaf(ags[2][k], w, a2);
        a3 = fmaf(ags[3][k], w, a3);
    }
    out[(size_t)(n0 + 0) * EMB + j] = x[(size_t)(n0 + 0) * EMB + j] + a0;
    out[(size_t)(n0 + 1) * EMB + j] = x[(size_t)(n0 + 1) * EMB + j] + a1;
    out[(size_t)(n0 + 2) * EMB + j] = x[(size_t)(n0 + 2) * EMB + j] + a2;
    out[(size_t)(n0 + 3) * EMB + j] = x[(size_t)(n0 + 3) * EMB + j] + a3;
}

extern "C" void kernel_launch(void* const* d_in, const int* in_sizes, int n_in,
                              void* d_out, int out_size) {
    const float* x      = (const float*)d_in[0];
    const float* cst    = (const float*)d_in[1];
    const float* rb     = (const float*)d_in[2];
    const float* shb    = (const float*)d_in[3];
    const int*   idx_s  = (const int*)  d_in[4];
    const int*   idx_t  = (const int*)  d_in[5];
    const int*   tri_k  = (const int*)  d_in[6];
    const int*   eks    = (const int*)  d_in[7];
    const int*   est    = (const int*)  d_in[8];
    const float* W_node = (const float*)d_in[9];
    const float* b_node = (const float*)d_in[10];
    const float* W_c1   = (const float*)d_in[11];
    const float* W_c2   = (const float*)d_in[12];
    const float* W_three= (const float*)d_in[13];
    const float* W_basis= (const float*)d_in[14];
    const float* W_n1   = (const float*)d_in[15];
    const float* b_n1   = (const float*)d_in[16];
    const float* W_n2   = (const float*)d_in[17];
    const float* b_n2   = (const float*)d_in[18];
    const float* W_out  = (const float*)d_in[19];
    float* out = (float*)d_out;

    cudaFuncSetAttribute(k_edge,    cudaFuncAttributeMaxDynamicSharedMemorySize, EDGE_SMEM_BYTES);
    cudaFuncSetAttribute(k_cst_mma, cudaFuncAttributeMaxDynamicSharedMemorySize, CST_SMEM_BYTES);

    k_node<<<N_NODES / 4, 128>>>(x, W_node, b_node);
    k_prepw<<<1, 256>>>(W_c1, W_c2);
    k_cst_mma<<<(N_EDGES * NORB) / 128, 256, CST_SMEM_BYTES>>>(cst, rb);
    k_tri <<<(N_TRI * 32) / 256, 256>>>(rb, shb, tri_k, eks, est);
    k_edge<<<(N_EDGES + 127) / 128, 256, EDGE_SMEM_BYTES>>>(idx_s, idx_t, W_three, W_basis,
                                                            W_n1, b_n1, W_n2, b_n2);
    k_out <<<N_NODES / 4, 128>>>(x, W_out, out);
}